// round 1
// baseline (speedup 1.0000x reference)
#include <cuda_runtime.h>
#include <cstdint>

// ---------------- constants (STATS are fixed) ----------------
#define S1 (3.5f/255.0f)   // conv1 stat (-0.5, 3.0)
#define ZP1 36.0f          // trunc(0.5/S1)
#define S2 (6.0f/255.0f)   // conv2 stat (0,6), zp=0
#define S3 (8.0f/255.0f)   // fc1 stat (0,8), zp=0
#define S4 (10.0f/255.0f)  // fc2 stat (0,10), zp=0

#define BATCH 4096

// ---------------- device scratch (no allocation allowed) ----------------
__device__ unsigned g_mmkey[12];                       // per-tensor ordered min/max keys
__device__ float g_w1t[25*20];                          // conv1 W_eff transposed [k][c]
__device__ float g_b1eff[20];
__device__ float g_w2t[500*64];                         // conv2 W_eff transposed [k=ci*25+ky*5+kx][c pad 64]
__device__ float g_b2eff[64];
__device__ float g_fc1t[800*512];                       // fc1 W_eff transposed [k][n pad 512]
__device__ float g_b3eff[512];
__device__ unsigned char g_act1[BATCH*20*12*12];        // after conv1+pool (u8 q-values)
__device__ unsigned char g_act2[BATCH*50*4*4];          // after conv2+pool (u8 q-values)
__device__ float g_xf[BATCH*500];                       // dequantized fc1 output

// ---------------- helpers ----------------
__device__ __forceinline__ float clip255(float v){ return fminf(fmaxf(v, 0.0f), 255.0f); }

__device__ __forceinline__ unsigned f2key(float f){
    unsigned u = __float_as_uint(f);
    return (u & 0x80000000u) ? ~u : (u | 0x80000000u);
}
__device__ __forceinline__ float key2f(unsigned k){
    return __uint_as_float((k & 0x80000000u) ? (k & 0x7fffffffu) : ~k);
}
__device__ __forceinline__ void get_sz(int t, float& scale, float& zp){
    float mn = key2f(g_mmkey[2*t]);
    float mx = key2f(g_mmkey[2*t+1]);
    scale = (mx - mn) / 255.0f;
    zp = truncf(clip255(-mn / scale));
}
__device__ __forceinline__ float qround(float v, float scale, float zp){
    return rintf(clip255(zp + v / scale));
}

// ---------------- kernel: init min/max keys ----------------
__global__ void init_mm_kernel(){
    int t = threadIdx.x;
    if (t < 6){
        g_mmkey[2*t]   = 0xFFFFFFFFu;  // min slot
        g_mmkey[2*t+1] = 0u;           // max slot
    }
}

// ---------------- kernel: min/max over the 6 quantized param tensors ----------------
__global__ void minmax_kernel(const float* __restrict__ c1w, const float* __restrict__ c1b,
                              const float* __restrict__ c2w, const float* __restrict__ c2b,
                              const float* __restrict__ f1w, const float* __restrict__ f1b){
    __shared__ unsigned smn[256], smx[256];
    int b = blockIdx.x, tid = threadIdx.x;
    const float* p; int n, t, sub, nb;
    if (b < 64)      { t = 4; p = f1w; n = 400000; sub = b;      nb = 64; }
    else if (b < 68) { t = 2; p = c2w; n = 25000;  sub = b - 64; nb = 4;  }
    else if (b == 68){ t = 0; p = c1w; n = 500;    sub = 0;      nb = 1;  }
    else if (b == 69){ t = 1; p = c1b; n = 20;     sub = 0;      nb = 1;  }
    else if (b == 70){ t = 3; p = c2b; n = 50;     sub = 0;      nb = 1;  }
    else             { t = 5; p = f1b; n = 500;    sub = 0;      nb = 1;  }

    unsigned lmin = 0xFFFFFFFFu, lmax = 0u;
    for (int i = sub*256 + tid; i < n; i += nb*256){
        unsigned k = f2key(p[i]);
        lmin = min(lmin, k);
        lmax = max(lmax, k);
    }
    smn[tid] = lmin; smx[tid] = lmax;
    __syncthreads();
    for (int s = 128; s; s >>= 1){
        if (tid < s){
            smn[tid] = min(smn[tid], smn[tid+s]);
            smx[tid] = max(smx[tid], smx[tid+s]);
        }
        __syncthreads();
    }
    if (tid == 0){
        atomicMin(&g_mmkey[2*t],   smn[0]);
        atomicMax(&g_mmkey[2*t+1], smx[0]);
    }
}

// ---------------- kernel: build effective weights/biases ----------------
// W_eff = scale_x * scale_w * (wq - zp_w);  B_eff = scale_b * (bq + zp_b)  (faithful '+')
__global__ void effs_kernel(const float* __restrict__ c1w, const float* __restrict__ c1b,
                            const float* __restrict__ c2w, const float* __restrict__ c2b,
                            const float* __restrict__ f1w, const float* __restrict__ f1b){
    int idx = blockIdx.x*blockDim.x + threadIdx.x;
    if (idx < 500){                                       // conv1 W -> [k=25][c=20]
        int k = idx / 20, c = idx % 20;
        float s, z; get_sz(0, s, z);
        g_w1t[idx] = (S1 * s) * (qround(c1w[c*25 + k], s, z) - z);
    } else if (idx < 520){                                // conv1 b
        int c = idx - 500;
        float s, z; get_sz(1, s, z);
        g_b1eff[c] = s * (qround(c1b[c], s, z) + z);
    } else if (idx < 32520){                              // conv2 W -> [k=500][c pad 64]
        int e = idx - 520;
        int k = e / 64, c = e % 64;
        float val = 0.0f;
        if (c < 50){
            float s, z; get_sz(2, s, z);
            val = (S2 * s) * (qround(c2w[c*500 + k], s, z) - z);
        }
        g_w2t[e] = val;
    } else if (idx < 32584){                              // conv2 b pad 64
        int c = idx - 32520;
        float val = 0.0f;
        if (c < 50){
            float s, z; get_sz(3, s, z);
            val = s * (qround(c2b[c], s, z) + z);
        }
        g_b2eff[c] = val;
    } else if (idx < 442184){                             // fc1 W -> [k=800][n pad 512]
        int e = idx - 32584;
        int k = e / 512, n = e % 512;
        float val = 0.0f;
        if (n < 500){
            float s, z; get_sz(4, s, z);
            val = (S3 * s) * (qround(f1w[n*800 + k], s, z) - z);
        }
        g_fc1t[e] = val;
    } else if (idx < 442696){                             // fc1 b pad 512
        int n = idx - 442184;
        float val = 0.0f;
        if (n < 500){
            float s, z; get_sz(5, s, z);
            val = s * (qround(f1b[n], s, z) + z);
        }
        g_b3eff[n] = val;
    }
}

// ---------------- kernel: quantize input + conv1 + quant + 2x2 pool ----------------
// one image per block, 384 threads (360 active for conv: 24 y * 3 xgrp * 5 chgrp)
__global__ void __launch_bounds__(384) conv1_kernel(const float* __restrict__ x){
    __shared__ float xs[28*32];          // X = q0 - 36, rows padded to 32 floats
    __shared__ float ws[25*20];          // W_eff transposed [k][c]
    __shared__ float bs[20];
    __shared__ unsigned char q1[20*24*24];

    int img = blockIdx.x, tid = threadIdx.x;
    const float* xi = x + img*784;
    for (int i = tid; i < 784; i += 384){
        int r = i / 28, c = i % 28;
        float q0 = rintf(clip255(ZP1 + xi[i] / S1));
        xs[r*32 + c] = q0 - ZP1;
    }
    for (int i = tid; i < 500; i += 384) ws[i] = g_w1t[i];
    if (tid < 20) bs[tid] = g_b1eff[tid];
    __syncthreads();

    if (tid < 360){
        int y = tid / 15, r = tid % 15;
        int xg = r / 5, cg = r % 5;      // 8 x-positions, 4 channels
        float acc[8][4];
        #pragma unroll
        for (int xx = 0; xx < 8; xx++)
            #pragma unroll
            for (int c = 0; c < 4; c++) acc[xx][c] = bs[cg*4 + c];

        #pragma unroll
        for (int ky = 0; ky < 5; ky++){
            const float4* xr4 = (const float4*)(xs + (y + ky)*32 + xg*8);
            float4 a0 = xr4[0], a1 = xr4[1], a2 = xr4[2];
            float xv[12] = {a0.x,a0.y,a0.z,a0.w, a1.x,a1.y,a1.z,a1.w, a2.x,a2.y,a2.z,a2.w};
            #pragma unroll
            for (int kx = 0; kx < 5; kx++){
                float4 w = *(const float4*)(ws + (ky*5 + kx)*20 + cg*4);
                #pragma unroll
                for (int xx = 0; xx < 8; xx++){
                    float xvv = xv[xx + kx];
                    acc[xx][0] += xvv * w.x;
                    acc[xx][1] += xvv * w.y;
                    acc[xx][2] += xvv * w.z;
                    acc[xx][3] += xvv * w.w;
                }
            }
        }
        #pragma unroll
        for (int c = 0; c < 4; c++)
            #pragma unroll
            for (int xx = 0; xx < 8; xx++){
                float v = fmodf(rintf(fmaxf(acc[xx][c] / S2, 0.0f)), 256.0f);
                q1[(cg*4 + c)*576 + y*24 + xg*8 + xx] = (unsigned char)v;
            }
    }
    __syncthreads();

    for (int i = tid; i < 2880; i += 384){
        int c = i / 144, rr = (i % 144) / 12, cc = i % 12;
        const unsigned char* b0 = q1 + c*576 + (2*rr)*24 + 2*cc;
        unsigned char m = max(max(b0[0], b0[1]), max(b0[24], b0[25]));
        g_act1[((img*20 + c)*12 + rr)*12 + cc] = m;
    }
}

// ---------------- kernel: conv2 + quant + 2x2 pool ----------------
// block = 4 images x one 32-channel half; 256 threads; dynamic smem
#define C2_W_BYTES  (500*32*4)    // 64000
#define C2_X_BYTES  (4*20*12*12)  // 11520
#define C2_Q_BYTES  (4*32*8*8)    // 8192
#define C2_SMEM     (C2_W_BYTES + C2_X_BYTES + C2_Q_BYTES)

__global__ void __launch_bounds__(256) conv2_kernel(){
    extern __shared__ char sm[];
    float* Ws = (float*)sm;
    unsigned char* Xs = (unsigned char*)(sm + C2_W_BYTES);
    unsigned char* q2 = (unsigned char*)(sm + C2_W_BYTES + C2_X_BYTES);

    int tid = threadIdx.x;
    int imgbase = blockIdx.x * 4;
    int chblk = blockIdx.y;              // 0 or 1 -> channels [0,32) or [32,64)

    // load weights tile (500 x 32 floats)
    {
        const float4* wsrc = (const float4*)g_w2t;   // rows of 16 float4
        float4* wdst = (float4*)Ws;
        for (int i = tid; i < 4000; i += 256){
            int row = i >> 3, c4 = i & 7;
            wdst[row*8 + c4] = wsrc[row*16 + chblk*8 + c4];
        }
    }
    // load 4 images of act1 (u8)
    {
        const uint4* xsrc = (const uint4*)(g_act1 + imgbase*2880);
        uint4* xdst = (uint4*)Xs;
        for (int i = tid; i < 720; i += 256) xdst[i] = xsrc[i];
    }
    __syncthreads();

    int li = tid / 64;                   // local image
    int t  = tid % 64;
    int y  = t / 8;                      // conv output row 0..7
    int cg = t % 8;                      // channel group of 4
    float4 b = *(const float4*)(g_b2eff + chblk*32 + cg*4);

    float acc[8][4];
    #pragma unroll
    for (int xx = 0; xx < 8; xx++){
        acc[xx][0] = b.x; acc[xx][1] = b.y; acc[xx][2] = b.z; acc[xx][3] = b.w;
    }

    #pragma unroll 1
    for (int ci = 0; ci < 20; ci++){
        #pragma unroll
        for (int ky = 0; ky < 5; ky++){
            const unsigned* xr = (const unsigned*)(Xs + ((li*20 + ci)*12 + (y + ky))*12);
            unsigned u0 = xr[0], u1 = xr[1], u2 = xr[2];
            float xv[12];
            #pragma unroll
            for (int j = 0; j < 4; j++){
                xv[j]     = (float)((u0 >> (8*j)) & 0xffu);
                xv[4 + j] = (float)((u1 >> (8*j)) & 0xffu);
                xv[8 + j] = (float)((u2 >> (8*j)) & 0xffu);
            }
            #pragma unroll
            for (int kx = 0; kx < 5; kx++){
                float4 w = ((const float4*)Ws)[(ci*25 + ky*5 + kx)*8 + cg];
                #pragma unroll
                for (int xx = 0; xx < 8; xx++){
                    float xvv = xv[xx + kx];
                    acc[xx][0] += xvv * w.x;
                    acc[xx][1] += xvv * w.y;
                    acc[xx][2] += xvv * w.z;
                    acc[xx][3] += xvv * w.w;
                }
            }
        }
    }

    #pragma unroll
    for (int c = 0; c < 4; c++)
        #pragma unroll
        for (int xx = 0; xx < 8; xx++){
            float v = fmodf(rintf(fmaxf(acc[xx][c] / S3, 0.0f)), 256.0f);
            q2[((li*32 + cg*4 + c)*8 + y)*8 + xx] = (unsigned char)v;
        }
    __syncthreads();

    for (int i = tid; i < 2048; i += 256){
        int im = i / 512, rest = i % 512;
        int c = rest / 16, pr = (rest % 16) / 4, pc = rest % 4;
        int gch = chblk*32 + c;
        if (gch < 50){
            const unsigned char* bp = q2 + ((im*32 + c)*8 + 2*pr)*8 + 2*pc;
            unsigned char m = max(max(bp[0], bp[1]), max(bp[8], bp[9]));
            g_act2[(((imgbase + im)*50 + gch)*4 + pr)*4 + pc] = m;
        }
    }
}

// ---------------- kernel: fc1 GEMM + quant + dequant ----------------
// M=4096, K=800, N=512(pad). Block tile 64x64, K-tile 32, thread tile 4x4.
__global__ void __launch_bounds__(256) fc1_kernel(){
    __shared__ float Xt[32][68];   // [k][m]
    __shared__ float Wt[32][68];   // [k][n]
    int tid = threadIdx.x;
    int m0 = blockIdx.x * 64, n0 = blockIdx.y * 64;
    int tx = tid % 16, ty = tid / 16;
    float acc[4][4] = {};

    #pragma unroll 1
    for (int kt = 0; kt < 25; kt++){
        int k0 = kt * 32;
        // X tile: 64 rows x 32 u8 -> transposed float
        {
            int r = tid / 4, seg = tid % 4;
            uint2 u = *(const uint2*)(g_act2 + (m0 + r)*800 + k0 + seg*8);
            #pragma unroll
            for (int j = 0; j < 4; j++){
                Xt[seg*8 + j][r]     = (float)((u.x >> (8*j)) & 0xffu);
                Xt[seg*8 + 4 + j][r] = (float)((u.y >> (8*j)) & 0xffu);
            }
        }
        // W tile: 32 x 64 floats
        #pragma unroll
        for (int i = tid; i < 512; i += 256){
            int kr = i / 16, nc = i % 16;
            *(float4*)&Wt[kr][nc*4] = *(const float4*)(g_fc1t + (k0 + kr)*512 + n0 + nc*4);
        }
        __syncthreads();

        #pragma unroll
        for (int kk = 0; kk < 32; kk++){
            float4 a = *(float4*)&Xt[kk][ty*4];
            float4 bb = *(float4*)&Wt[kk][tx*4];
            acc[0][0] += a.x*bb.x; acc[0][1] += a.x*bb.y; acc[0][2] += a.x*bb.z; acc[0][3] += a.x*bb.w;
            acc[1][0] += a.y*bb.x; acc[1][1] += a.y*bb.y; acc[1][2] += a.y*bb.z; acc[1][3] += a.y*bb.w;
            acc[2][0] += a.z*bb.x; acc[2][1] += a.z*bb.y; acc[2][2] += a.z*bb.z; acc[2][3] += a.z*bb.w;
            acc[3][0] += a.w*bb.x; acc[3][1] += a.w*bb.y; acc[3][2] += a.w*bb.z; acc[3][3] += a.w*bb.w;
        }
        __syncthreads();
    }

    #pragma unroll
    for (int i = 0; i < 4; i++){
        int m = m0 + ty*4 + i;
        #pragma unroll
        for (int j = 0; j < 4; j++){
            int n = n0 + tx*4 + j;
            if (n < 500){
                float yv = acc[i][j] + g_b3eff[n];
                float q = fmodf(rintf(fmaxf(yv / S4, 0.0f)), 256.0f);
                g_xf[m*500 + n] = S4 * q;
            }
        }
    }
}

// ---------------- kernel: fc2 + log_softmax ----------------
__global__ void __launch_bounds__(128) fc2_kernel(const float* __restrict__ w,
                                                  const float* __restrict__ bias,
                                                  float* __restrict__ out){
    __shared__ float ws[5000];   // [k=500][j=10]
    __shared__ float bsh[10];
    int tid = threadIdx.x;
    for (int i = tid; i < 5000; i += 128){
        int j = i / 500, k = i % 500;
        ws[k*10 + j] = w[i];
    }
    if (tid < 10) bsh[tid] = bias[tid];
    __syncthreads();

    int warp = tid / 32, lane = tid % 32;
    int row = blockIdx.x*4 + warp;
    float acc[10];
    #pragma unroll
    for (int j = 0; j < 10; j++) acc[j] = 0.0f;

    for (int k = lane; k < 500; k += 32){
        float xv = g_xf[row*500 + k];
        const float* wr = ws + k*10;
        #pragma unroll
        for (int j = 0; j < 10; j++) acc[j] += xv * wr[j];
    }
    #pragma unroll
    for (int j = 0; j < 10; j++){
        #pragma unroll
        for (int off = 16; off; off >>= 1)
            acc[j] += __shfl_down_sync(0xffffffffu, acc[j], off);
    }
    if (lane == 0){
        float l[10], m = -1e30f;
        #pragma unroll
        for (int j = 0; j < 10; j++){ l[j] = acc[j] + bsh[j]; m = fmaxf(m, l[j]); }
        float s = 0.0f;
        #pragma unroll
        for (int j = 0; j < 10; j++) s += expf(l[j] - m);
        float ls = logf(s);
        #pragma unroll
        for (int j = 0; j < 10; j++) out[row*10 + j] = l[j] - m - ls;
    }
}

// ---------------- launch ----------------
extern "C" void kernel_launch(void* const* d_in, const int* in_sizes, int n_in,
                              void* d_out, int out_size){
    const float* x   = (const float*)d_in[0];
    const float* c1w = (const float*)d_in[1];
    const float* c1b = (const float*)d_in[2];
    const float* c2w = (const float*)d_in[3];
    const float* c2b = (const float*)d_in[4];
    const float* f1w = (const float*)d_in[5];
    const float* f1b = (const float*)d_in[6];
    const float* f2w = (const float*)d_in[7];
    const float* f2b = (const float*)d_in[8];

    cudaFuncSetAttribute(conv2_kernel, cudaFuncAttributeMaxDynamicSharedMemorySize, C2_SMEM);

    init_mm_kernel<<<1, 32>>>();
    minmax_kernel<<<72, 256>>>(c1w, c1b, c2w, c2b, f1w, f1b);
    effs_kernel<<<1730, 256>>>(c1w, c1b, c2w, c2b, f1w, f1b);
    conv1_kernel<<<BATCH, 384>>>(x);
    conv2_kernel<<<dim3(BATCH/4, 2), 256, C2_SMEM>>>();
    fc1_kernel<<<dim3(BATCH/64, 8), 256>>>();
    fc2_kernel<<<BATCH/4, 128>>>(f2w, f2b, (float*)d_out);
}

// round 2
// speedup vs baseline: 2.0723x; 2.0723x over previous
#include <cuda_runtime.h>
#include <cstdint>

// ---------------- constants (STATS are fixed) ----------------
#define S1 (3.5f/255.0f)   // conv1 stat (-0.5, 3.0)
#define ZP1 36.0f          // trunc(0.5/S1)
#define S2 (6.0f/255.0f)   // conv2 stat (0,6), zp=0
#define S3 (8.0f/255.0f)   // fc1 stat (0,8), zp=0
#define S4 (10.0f/255.0f)  // fc2 stat (0,10), zp=0

#define BATCH 4096
#define C2_CPAD 52

// ---------------- device scratch ----------------
__device__ unsigned g_mmkey[12];
__device__ __align__(16) float g_w1t[25*20];            // conv1 W_eff transposed [k][c] (fp32 path)
__device__ float g_b1eff[20];
__device__ __align__(16) unsigned g_w2q[5*25*C2_CPAD];  // conv2 wq packed: [ci_pack][ky*5+kx][c]
__device__ float g_b2eff[C2_CPAD];
__device__ __align__(16) unsigned g_fc1q[200*512];      // fc1 wq packed: [k_pack][n pad 512]
__device__ float g_b3eff[512];
__device__ __align__(16) unsigned char g_act1[BATCH*12*5*12*4]; // conv1+pool, ch-packed [img][y][p][x] u32
__device__ __align__(16) unsigned char g_act2[BATCH*50*4*4];    // conv2+pool, [img][ch][pr][pc]
__device__ int g_rowsum[BATCH];                          // per-image sum of act2
__device__ float g_xf[BATCH*500];

// ---------------- helpers ----------------
__device__ __forceinline__ float clip255(float v){ return fminf(fmaxf(v, 0.0f), 255.0f); }
__device__ __forceinline__ unsigned f2key(float f){
    unsigned u = __float_as_uint(f);
    return (u & 0x80000000u) ? ~u : (u | 0x80000000u);
}
__device__ __forceinline__ float key2f(unsigned k){
    return __uint_as_float((k & 0x80000000u) ? (k & 0x7fffffffu) : ~k);
}
__device__ __forceinline__ void get_sz(int t, float& scale, float& zp){
    float mn = key2f(g_mmkey[2*t]);
    float mx = key2f(g_mmkey[2*t+1]);
    scale = (mx - mn) / 255.0f;
    zp = truncf(clip255(-mn / scale));
}
__device__ __forceinline__ float qround(float v, float scale, float zp){
    return rintf(clip255(zp + v / scale));
}

// ---------------- init min/max ----------------
__global__ void init_mm_kernel(){
    int t = threadIdx.x;
    if (t < 6){ g_mmkey[2*t] = 0xFFFFFFFFu; g_mmkey[2*t+1] = 0u; }
}

// ---------------- min/max over 6 param tensors ----------------
__global__ void minmax_kernel(const float* __restrict__ c1w, const float* __restrict__ c1b,
                              const float* __restrict__ c2w, const float* __restrict__ c2b,
                              const float* __restrict__ f1w, const float* __restrict__ f1b){
    __shared__ unsigned smn[256], smx[256];
    int b = blockIdx.x, tid = threadIdx.x;
    const float* p; int n, t, sub, nb;
    if (b < 64)      { t = 4; p = f1w; n = 400000; sub = b;      nb = 64; }
    else if (b < 68) { t = 2; p = c2w; n = 25000;  sub = b - 64; nb = 4;  }
    else if (b == 68){ t = 0; p = c1w; n = 500;    sub = 0;      nb = 1;  }
    else if (b == 69){ t = 1; p = c1b; n = 20;     sub = 0;      nb = 1;  }
    else if (b == 70){ t = 3; p = c2b; n = 50;     sub = 0;      nb = 1;  }
    else             { t = 5; p = f1b; n = 500;    sub = 0;      nb = 1;  }

    unsigned lmin = 0xFFFFFFFFu, lmax = 0u;
    for (int i = sub*256 + tid; i < n; i += nb*256){
        unsigned k = f2key(p[i]);
        lmin = min(lmin, k); lmax = max(lmax, k);
    }
    smn[tid] = lmin; smx[tid] = lmax;
    __syncthreads();
    for (int s = 128; s; s >>= 1){
        if (tid < s){
            smn[tid] = min(smn[tid], smn[tid+s]);
            smx[tid] = max(smx[tid], smx[tid+s]);
        }
        __syncthreads();
    }
    if (tid == 0){
        atomicMin(&g_mmkey[2*t],   smn[0]);
        atomicMax(&g_mmkey[2*t+1], smx[0]);
    }
}

// ---------------- build effective / packed weights ----------------
__global__ void effs_kernel(const float* __restrict__ c1w, const float* __restrict__ c1b,
                            const float* __restrict__ c2w, const float* __restrict__ c2b,
                            const float* __restrict__ f1w, const float* __restrict__ f1b){
    int idx = blockIdx.x*blockDim.x + threadIdx.x;
    if (idx < 500){                                       // conv1 W_eff fp32 [k=25][c=20]
        int k = idx / 20, c = idx % 20;
        float s, z; get_sz(0, s, z);
        g_w1t[idx] = (S1 * s) * (qround(c1w[c*25 + k], s, z) - z);
    } else if (idx < 520){                                // conv1 b
        int c = idx - 500;
        float s, z; get_sz(1, s, z);
        g_b1eff[c] = s * (qround(c1b[c], s, z) + z);
    } else if (idx < 7020){                               // conv2 wq packed [p][r][c]
        int e = idx - 520;
        int p = e / (25*C2_CPAD), r = (e / C2_CPAD) % 25, c = e % C2_CPAD;
        unsigned pk = 0u;
        if (c < 50){
            float s, z; get_sz(2, s, z);
            #pragma unroll
            for (int j = 0; j < 4; j++){
                int ci = p*4 + j;
                unsigned wq = (unsigned)qround(c2w[c*500 + ci*25 + r], s, z);
                pk |= (wq & 0xffu) << (8*j);
            }
        }
        g_w2q[e] = pk;
    } else if (idx < 7072){                               // conv2 b pad
        int c = idx - 7020;
        float val = 0.0f;
        if (c < 50){
            float s, z; get_sz(3, s, z);
            val = s * (qround(c2b[c], s, z) + z);
        }
        g_b2eff[c] = val;
    } else if (idx < 109472){                             // fc1 wq packed [kp=200][n pad 512]
        int e = idx - 7072;
        int kp = e / 512, n = e % 512;
        unsigned pk = 0u;
        if (n < 500){
            float s, z; get_sz(4, s, z);
            #pragma unroll
            for (int j = 0; j < 4; j++){
                int k = kp*4 + j;
                unsigned wq = (unsigned)qround(f1w[n*800 + k], s, z);
                pk |= (wq & 0xffu) << (8*j);
            }
        }
        g_fc1q[e] = pk;
    } else if (idx < 109984){                             // fc1 b pad 512
        int n = idx - 109472;
        float val = 0.0f;
        if (n < 500){
            float s, z; get_sz(5, s, z);
            val = s * (qround(f1b[n], s, z) + z);
        }
        g_b3eff[n] = val;
    }
}

// ---------------- conv1 (fp32) + quant + pool; output channel-packed ----------------
__global__ void __launch_bounds__(384) conv1_kernel(const float* __restrict__ x){
    __shared__ float xs[28*32];
    __shared__ float ws[25*20];
    __shared__ float bs[20];
    __shared__ unsigned char q1[20*24*24];

    int img = blockIdx.x, tid = threadIdx.x;
    const float* xi = x + img*784;
    for (int i = tid; i < 784; i += 384){
        int r = i / 28, c = i % 28;
        float q0 = rintf(clip255(ZP1 + xi[i] / S1));
        xs[r*32 + c] = q0 - ZP1;
    }
    for (int i = tid; i < 500; i += 384) ws[i] = g_w1t[i];
    if (tid < 20) bs[tid] = g_b1eff[tid];
    __syncthreads();

    if (tid < 360){
        int y = tid / 15, r = tid % 15;
        int xg = r / 5, cg = r % 5;
        float acc[8][4];
        #pragma unroll
        for (int xx = 0; xx < 8; xx++)
            #pragma unroll
            for (int c = 0; c < 4; c++) acc[xx][c] = bs[cg*4 + c];

        #pragma unroll
        for (int ky = 0; ky < 5; ky++){
            const float4* xr4 = (const float4*)(xs + (y + ky)*32 + xg*8);
            float4 a0 = xr4[0], a1 = xr4[1], a2 = xr4[2];
            float xv[12] = {a0.x,a0.y,a0.z,a0.w, a1.x,a1.y,a1.z,a1.w, a2.x,a2.y,a2.z,a2.w};
            #pragma unroll
            for (int kx = 0; kx < 5; kx++){
                float4 w = *(const float4*)(ws + (ky*5 + kx)*20 + cg*4);
                #pragma unroll
                for (int xx = 0; xx < 8; xx++){
                    float xvv = xv[xx + kx];
                    acc[xx][0] += xvv * w.x;
                    acc[xx][1] += xvv * w.y;
                    acc[xx][2] += xvv * w.z;
                    acc[xx][3] += xvv * w.w;
                }
            }
        }
        #pragma unroll
        for (int c = 0; c < 4; c++)
            #pragma unroll
            for (int xx = 0; xx < 8; xx++){
                float v = fmodf(rintf(fmaxf(acc[xx][c] / S2, 0.0f)), 256.0f);
                q1[(cg*4 + c)*576 + y*24 + xg*8 + xx] = (unsigned char)v;
            }
    }
    __syncthreads();

    // pool 2x2 -> write channel-packed: byte ((img*12+rr)*5 + c/4)*48 + cc*4 + (c%4)
    for (int i = tid; i < 2880; i += 384){
        int c = i / 144, rr = (i % 144) / 12, cc = i % 12;
        const unsigned char* b0 = q1 + c*576 + (2*rr)*24 + 2*cc;
        unsigned char m = max(max(b0[0], b0[1]), max(b0[24], b0[25]));
        g_act1[((img*12 + rr)*5 + (c >> 2))*48 + cc*4 + (c & 3)] = m;
    }
}

// ---------------- conv2 via dp4a + quant + pool ----------------
// block = 2 images, all channels (pad 52). 256 threads, 208 compute.
__global__ void __launch_bounds__(256) conv2_kernel(){
    __shared__ unsigned Wq_s[5*25*C2_CPAD];   // 26000 B
    __shared__ unsigned Xs[2*12*5*12];        // 5760 B   [li][y][p][x]
    __shared__ unsigned Sw[2*8*8];            // window sums
    __shared__ unsigned char q2[2*C2_CPAD*64];

    int tid = threadIdx.x;
    int imgbase = blockIdx.x * 2;

    // load packed weights (6500 u32 = 1625 uint4)
    for (int i = tid; i < 1625; i += 256)
        ((uint4*)Wq_s)[i] = ((const uint4*)g_w2q)[i];
    // load 2 images of act1 (already channel-packed, contiguous)
    {
        const uint4* xsrc = (const uint4*)(g_act1 + imgbase*2880);
        for (int i = tid; i < 360; i += 256) ((uint4*)Xs)[i] = xsrc[i];
    }
    __syncthreads();

    // window sums: 2 imgs x 8 x 8 outputs
    if (tid < 128){
        int li = tid / 64, t = tid % 64;
        int oy = t / 8, ox = t % 8;
        unsigned s = 0;
        for (int ky = 0; ky < 5; ky++)
            for (int p = 0; p < 5; p++){
                const unsigned* row = &Xs[((li*12 + oy + ky)*5 + p)*12];
                #pragma unroll
                for (int kx = 0; kx < 5; kx++)
                    s = __dp4a(row[ox + kx], 0x01010101u, s);
            }
        Sw[li*64 + oy*8 + ox] = s;
    }

    int active = tid < 208;
    int li = 0, y = 0, cg = 0;
    unsigned acc[8][4];
    #pragma unroll
    for (int xx = 0; xx < 8; xx++)
        #pragma unroll
        for (int c = 0; c < 4; c++) acc[xx][c] = 0u;

    if (active){
        li = tid / 104;
        int t = tid % 104;
        y = t / 13; cg = t % 13;

        #pragma unroll 1
        for (int p = 0; p < 5; p++){
            #pragma unroll
            for (int ky = 0; ky < 5; ky++){
                const uint4* xr4 = (const uint4*)&Xs[((li*12 + y + ky)*5 + p)*12];
                uint4 a0 = xr4[0], a1 = xr4[1], a2 = xr4[2];
                unsigned xv[12] = {a0.x,a0.y,a0.z,a0.w, a1.x,a1.y,a1.z,a1.w, a2.x,a2.y,a2.z,a2.w};
                #pragma unroll
                for (int kx = 0; kx < 5; kx++){
                    uint4 w = *(const uint4*)&Wq_s[(p*25 + ky*5 + kx)*C2_CPAD + cg*4];
                    #pragma unroll
                    for (int xx = 0; xx < 8; xx++){
                        unsigned xvv = xv[xx + kx];
                        acc[xx][0] = __dp4a(xvv, w.x, acc[xx][0]);
                        acc[xx][1] = __dp4a(xvv, w.y, acc[xx][1]);
                        acc[xx][2] = __dp4a(xvv, w.z, acc[xx][2]);
                        acc[xx][3] = __dp4a(xvv, w.w, acc[xx][3]);
                    }
                }
            }
        }
    }
    __syncthreads();   // Sw visible to all

    if (active){
        float s2w, z2w; get_sz(2, s2w, z2w);
        float S2s = S2 * s2w;
        int zp2 = (int)z2w;
        #pragma unroll
        for (int c = 0; c < 4; c++){
            int ch = cg*4 + c;
            float beff = g_b2eff[ch];
            #pragma unroll
            for (int xx = 0; xx < 8; xx++){
                int idiff = (int)acc[xx][c] - zp2 * (int)Sw[li*64 + y*8 + xx];
                float val = S2s * (float)idiff + beff;
                float q = fmodf(rintf(fmaxf(val / S3, 0.0f)), 256.0f);
                q2[((li*C2_CPAD + ch)*8 + y)*8 + xx] = (unsigned char)q;
            }
        }
    }
    __syncthreads();

    // pool 2x2 -> g_act2 [img][ch][pr][pc]
    for (int i = tid; i < 1600; i += 256){
        int im = i / 800, rest = i % 800;
        int ch = rest / 16, pr = (rest % 16) / 4, pc = rest % 4;
        const unsigned char* bp = q2 + ((im*C2_CPAD + ch)*8 + 2*pr)*8 + 2*pc;
        unsigned char m = max(max(bp[0], bp[1]), max(bp[8], bp[9]));
        g_act2[((imgbase + im)*50 + ch)*16 + pr*4 + pc] = m;
    }
}

// ---------------- rowsum of act2 (for fc1 zp correction) ----------------
__global__ void __launch_bounds__(256) rowsum_kernel(){
    int warp = threadIdx.x / 32, lane = threadIdx.x % 32;
    int row = blockIdx.x*8 + warp;
    const unsigned* xr = (const unsigned*)(g_act2) + row*200;
    unsigned s = 0;
    for (int k = lane; k < 200; k += 32) s = __dp4a(xr[k], 0x01010101u, s);
    #pragma unroll
    for (int off = 16; off; off >>= 1) s += __shfl_down_sync(0xffffffffu, s, off);
    if (lane == 0) g_rowsum[row] = (int)s;
}

// ---------------- fc1 via dp4a GEMM + quant + dequant ----------------
// M=4096, N=512(pad), K=200 u32. Block 64x64, K-tile 8 u32, thread 4x4.
__global__ void __launch_bounds__(256) fc1_kernel(){
    __shared__ unsigned Xt[8][68];   // [kp][m]
    __shared__ unsigned Wt[8][68];   // [kp][n]
    int tid = threadIdx.x;
    int m0 = blockIdx.x * 64, n0 = blockIdx.y * 64;
    int tx = tid % 16, ty = tid / 16;
    unsigned acc[4][4] = {};

    const unsigned* Xg = (const unsigned*)g_act2;

    #pragma unroll 1
    for (int kt = 0; kt < 25; kt++){
        int kp0 = kt * 8;
        {
            int r = tid / 4, seg = tid % 4;
            uint2 u = *(const uint2*)&Xg[(m0 + r)*200 + kp0 + seg*2];
            Xt[seg*2][r]     = u.x;
            Xt[seg*2 + 1][r] = u.y;
        }
        if (tid < 128){
            int kr = tid / 16, nc = tid % 16;
            *(uint4*)&Wt[kr][nc*4] = *(const uint4*)&g_fc1q[(kp0 + kr)*512 + n0 + nc*4];
        }
        __syncthreads();

        #pragma unroll
        for (int kk = 0; kk < 8; kk++){
            uint4 a = *(uint4*)&Xt[kk][ty*4];
            uint4 b = *(uint4*)&Wt[kk][tx*4];
            acc[0][0]=__dp4a(a.x,b.x,acc[0][0]); acc[0][1]=__dp4a(a.x,b.y,acc[0][1]); acc[0][2]=__dp4a(a.x,b.z,acc[0][2]); acc[0][3]=__dp4a(a.x,b.w,acc[0][3]);
            acc[1][0]=__dp4a(a.y,b.x,acc[1][0]); acc[1][1]=__dp4a(a.y,b.y,acc[1][1]); acc[1][2]=__dp4a(a.y,b.z,acc[1][2]); acc[1][3]=__dp4a(a.y,b.w,acc[1][3]);
            acc[2][0]=__dp4a(a.z,b.x,acc[2][0]); acc[2][1]=__dp4a(a.z,b.y,acc[2][1]); acc[2][2]=__dp4a(a.z,b.z,acc[2][2]); acc[2][3]=__dp4a(a.z,b.w,acc[2][3]);
            acc[3][0]=__dp4a(a.w,b.x,acc[3][0]); acc[3][1]=__dp4a(a.w,b.y,acc[3][1]); acc[3][2]=__dp4a(a.w,b.z,acc[3][2]); acc[3][3]=__dp4a(a.w,b.w,acc[3][3]);
        }
        __syncthreads();
    }

    float s3w, z3w; get_sz(4, s3w, z3w);
    float S3s = S3 * s3w;
    int zp3 = (int)z3w;

    #pragma unroll
    for (int i = 0; i < 4; i++){
        int m = m0 + ty*4 + i;
        int rs = g_rowsum[m];
        #pragma unroll
        for (int j = 0; j < 4; j++){
            int n = n0 + tx*4 + j;
            if (n < 500){
                float yv = S3s * (float)((int)acc[i][j] - zp3 * rs) + g_b3eff[n];
                float q = fmodf(rintf(fmaxf(yv / S4, 0.0f)), 256.0f);
                g_xf[m*500 + n] = S4 * q;
            }
        }
    }
}

// ---------------- fc2 + log_softmax ----------------
__global__ void __launch_bounds__(128) fc2_kernel(const float* __restrict__ w,
                                                  const float* __restrict__ bias,
                                                  float* __restrict__ out){
    __shared__ float ws[5000];
    __shared__ float bsh[10];
    int tid = threadIdx.x;
    for (int i = tid; i < 5000; i += 128){
        int j = i / 500, k = i % 500;
        ws[k*10 + j] = w[i];
    }
    if (tid < 10) bsh[tid] = bias[tid];
    __syncthreads();

    int warp = tid / 32, lane = tid % 32;
    int row = blockIdx.x*4 + warp;
    float acc[10];
    #pragma unroll
    for (int j = 0; j < 10; j++) acc[j] = 0.0f;

    for (int k = lane; k < 500; k += 32){
        float xv = g_xf[row*500 + k];
        const float* wr = ws + k*10;
        #pragma unroll
        for (int j = 0; j < 10; j++) acc[j] += xv * wr[j];
    }
    #pragma unroll
    for (int j = 0; j < 10; j++){
        #pragma unroll
        for (int off = 16; off; off >>= 1)
            acc[j] += __shfl_down_sync(0xffffffffu, acc[j], off);
    }
    if (lane == 0){
        float l[10], m = -1e30f;
        #pragma unroll
        for (int j = 0; j < 10; j++){ l[j] = acc[j] + bsh[j]; m = fmaxf(m, l[j]); }
        float s = 0.0f;
        #pragma unroll
        for (int j = 0; j < 10; j++) s += expf(l[j] - m);
        float ls = logf(s);
        #pragma unroll
        for (int j = 0; j < 10; j++) out[row*10 + j] = l[j] - m - ls;
    }
}

// ---------------- launch ----------------
extern "C" void kernel_launch(void* const* d_in, const int* in_sizes, int n_in,
                              void* d_out, int out_size){
    const float* x   = (const float*)d_in[0];
    const float* c1w = (const float*)d_in[1];
    const float* c1b = (const float*)d_in[2];
    const float* c2w = (const float*)d_in[3];
    const float* c2b = (const float*)d_in[4];
    const float* f1w = (const float*)d_in[5];
    const float* f1b = (const float*)d_in[6];
    const float* f2w = (const float*)d_in[7];
    const float* f2b = (const float*)d_in[8];

    init_mm_kernel<<<1, 32>>>();
    minmax_kernel<<<72, 256>>>(c1w, c1b, c2w, c2b, f1w, f1b);
    effs_kernel<<<430, 256>>>(c1w, c1b, c2w, c2b, f1w, f1b);
    conv1_kernel<<<BATCH, 384>>>(x);
    conv2_kernel<<<BATCH/2, 256>>>();
    rowsum_kernel<<<BATCH/8, 256>>>();
    fc1_kernel<<<dim3(BATCH/64, 8), 256>>>();
    fc2_kernel<<<BATCH/4, 128>>>(f2w, f2b, (float*)d_out);
}

// round 4
// speedup vs baseline: 2.2599x; 1.0905x over previous
#include <cuda_runtime.h>
#include <cstdint>

// ---------------- constants (STATS are fixed) ----------------
#define S1 (3.5f/255.0f)   // conv1 stat (-0.5, 3.0)
#define ZP1 36.0f          // trunc(0.5/S1)
#define INV_S2 42.5f       // 255/6  (exact)
#define INV_S3 31.875f     // 255/8  (exact)
#define INV_S4 25.5f       // 255/10 (exact)
#define S4 (10.0f/255.0f)

#define BATCH 4096
#define C2_CPAD 52

// ---------------- device scratch ----------------
__device__ unsigned g_mmkey[12];
__device__ __align__(16) unsigned g_w1lo[5*20];         // conv1 wq taps0-3 packed [ky][ch]
__device__ __align__(16) unsigned g_w1hi[5*20];         // conv1 wq tap4 packed  [ky][ch]
__device__ float g_c1c[20];                              // conv1 per-channel constant
__device__ __align__(16) unsigned g_w2q[5*25*C2_CPAD];  // conv2 wq packed: [ci_pack][ky*5+kx][c]
__device__ float g_b2eff[C2_CPAD];
__device__ __align__(16) unsigned g_fc1q[200*512];      // fc1 wq packed: [k_pack][n pad 512]
__device__ float g_b3eff[512];
__device__ __align__(16) unsigned char g_act1[BATCH*12*5*12*4]; // conv1+pool, ch-packed
__device__ __align__(16) unsigned char g_act2[BATCH*50*4*4];    // conv2+pool
__device__ int g_rowsum[BATCH];
__device__ float g_xf[BATCH*500];

// ---------------- helpers ----------------
__device__ __forceinline__ float clip255(float v){ return fminf(fmaxf(v, 0.0f), 255.0f); }
__device__ __forceinline__ unsigned f2key(float f){
    unsigned u = __float_as_uint(f);
    return (u & 0x80000000u) ? ~u : (u | 0x80000000u);
}
__device__ __forceinline__ float key2f(unsigned k){
    return __uint_as_float((k & 0x80000000u) ? (k & 0x7fffffffu) : ~k);
}
__device__ __forceinline__ void get_sz(int t, float& scale, float& zp){
    float mn = key2f(g_mmkey[2*t]);
    float mx = key2f(g_mmkey[2*t+1]);
    scale = (mx - mn) / 255.0f;
    zp = truncf(clip255(-mn / scale));
}
__device__ __forceinline__ float qround(float v, float scale, float zp){
    return rintf(clip255(zp + v / scale));
}

// ---------------- init min/max ----------------
__global__ void init_mm_kernel(){
    int t = threadIdx.x;
    if (t < 6){ g_mmkey[2*t] = 0xFFFFFFFFu; g_mmkey[2*t+1] = 0u; }
}

// ---------------- min/max over 6 param tensors ----------------
__global__ void minmax_kernel(const float* __restrict__ c1w, const float* __restrict__ c1b,
                              const float* __restrict__ c2w, const float* __restrict__ c2b,
                              const float* __restrict__ f1w, const float* __restrict__ f1b){
    __shared__ unsigned smn[256], smx[256];
    int b = blockIdx.x, tid = threadIdx.x;
    const float* p; int n, t, sub, nb;
    if (b < 64)      { t = 4; p = f1w; n = 400000; sub = b;      nb = 64; }
    else if (b < 68) { t = 2; p = c2w; n = 25000;  sub = b - 64; nb = 4;  }
    else if (b == 68){ t = 0; p = c1w; n = 500;    sub = 0;      nb = 1;  }
    else if (b == 69){ t = 1; p = c1b; n = 20;     sub = 0;      nb = 1;  }
    else if (b == 70){ t = 3; p = c2b; n = 50;     sub = 0;      nb = 1;  }
    else             { t = 5; p = f1b; n = 500;    sub = 0;      nb = 1;  }

    unsigned lmin = 0xFFFFFFFFu, lmax = 0u;
    for (int i = sub*256 + tid; i < n; i += nb*256){
        unsigned k = f2key(p[i]);
        lmin = min(lmin, k); lmax = max(lmax, k);
    }
    smn[tid] = lmin; smx[tid] = lmax;
    __syncthreads();
    for (int s = 128; s; s >>= 1){
        if (tid < s){
            smn[tid] = min(smn[tid], smn[tid+s]);
            smx[tid] = max(smx[tid], smx[tid+s]);
        }
        __syncthreads();
    }
    if (tid == 0){
        atomicMin(&g_mmkey[2*t],   smn[0]);
        atomicMax(&g_mmkey[2*t+1], smx[0]);
    }
}

// ---------------- build packed weights / constants ----------------
__global__ void effs_kernel(const float* __restrict__ c1w, const float* __restrict__ c1b,
                            const float* __restrict__ c2w, const float* __restrict__ c2b,
                            const float* __restrict__ f1w, const float* __restrict__ f1b){
    int idx = blockIdx.x*blockDim.x + threadIdx.x;
    if (idx < 100){                                       // conv1 packs [ky][ch]
        int ky = idx / 20, ch = idx % 20;
        float s, z; get_sz(0, s, z);
        unsigned lo = 0u;
        #pragma unroll
        for (int j = 0; j < 4; j++){
            unsigned wq = (unsigned)qround(c1w[ch*25 + ky*5 + j], s, z);
            lo |= (wq & 0xffu) << (8*j);
        }
        g_w1lo[idx] = lo;
        g_w1hi[idx] = (unsigned)qround(c1w[ch*25 + ky*5 + 4], s, z) & 0xffu;
    } else if (idx < 120){                                // conv1 per-channel const
        int ch = idx - 100;
        float s, z; get_sz(0, s, z);
        float wsum = 0.0f;
        for (int k = 0; k < 25; k++) wsum += qround(c1w[ch*25 + k], s, z);
        float sb, zb; get_sz(1, sb, zb);
        float beff = sb * (qround(c1b[ch], sb, zb) + zb);
        g_c1c[ch] = beff + (S1 * s) * (900.0f * z - 36.0f * wsum);
    } else if (idx < 6620){                               // conv2 wq packed [p][r][c]
        int e = idx - 120;
        int p = e / (25*C2_CPAD), r = (e / C2_CPAD) % 25, c = e % C2_CPAD;
        unsigned pk = 0u;
        if (c < 50){
            float s, z; get_sz(2, s, z);
            #pragma unroll
            for (int j = 0; j < 4; j++){
                int ci = p*4 + j;
                unsigned wq = (unsigned)qround(c2w[c*500 + ci*25 + r], s, z);
                pk |= (wq & 0xffu) << (8*j);
            }
        }
        g_w2q[e] = pk;
    } else if (idx < 6672){                               // conv2 b pad
        int c = idx - 6620;
        float val = 0.0f;
        if (c < 50){
            float s, z; get_sz(3, s, z);
            val = s * (qround(c2b[c], s, z) + z);
        }
        g_b2eff[c] = val;
    } else if (idx < 109072){                             // fc1 wq packed
        int e = idx - 6672;
        int kp = e / 512, n = e % 512;
        unsigned pk = 0u;
        if (n < 500){
            float s, z; get_sz(4, s, z);
            #pragma unroll
            for (int j = 0; j < 4; j++){
                int k = kp*4 + j;
                unsigned wq = (unsigned)qround(f1w[n*800 + k], s, z);
                pk |= (wq & 0xffu) << (8*j);
            }
        }
        g_fc1q[e] = pk;
    } else if (idx < 109584){                             // fc1 b pad 512
        int n = idx - 109072;
        float val = 0.0f;
        if (n < 500){
            float s, z; get_sz(5, s, z);
            val = s * (qround(f1b[n], s, z) + z);
        }
        g_b3eff[n] = val;
    }
}

// ---------------- conv1 via dp4a + quant + pool ----------------
// one image per block, 384 threads
__global__ void __launch_bounds__(384) conv1_kernel(const float* __restrict__ x){
    __shared__ unsigned q0u[28*8];        // q0 bytes, 8 u32 per row (last = pad 0)
    __shared__ unsigned Wn[28*28];        // sliding 4-byte windows per row
    __shared__ unsigned Ps[24*24];        // 5x5 window sums of q0
    __shared__ unsigned wlo_s[100], whi_s[100];
    __shared__ float cc_s[20];
    __shared__ unsigned char q1[20*24*24];

    int img = blockIdx.x, tid = threadIdx.x;
    const float* xi = x + img*784;

    // phase 1: quantize input to u8, packed u32 (row stride 8 u32, pad zero)
    if (tid < 224){
        int r = tid / 8, c4 = tid % 8;
        unsigned pk = 0u;
        if (c4 < 7){
            #pragma unroll
            for (int j = 0; j < 4; j++){
                float v = xi[r*28 + c4*4 + j];
                unsigned q = (unsigned)rintf(clip255(ZP1 + v / S1));
                pk |= (q & 0xffu) << (8*j);
            }
        }
        q0u[r*8 + c4] = pk;
    }
    for (int i = tid; i < 100; i += 384){ wlo_s[i] = g_w1lo[i]; whi_s[i] = g_w1hi[i]; }
    if (tid < 20) cc_s[tid] = g_c1c[tid];
    __syncthreads();

    // phase 2: build sliding windows Wn[r][x] = bytes q0[r][x..x+3]
    for (int i = tid; i < 784; i += 384){
        int r = i / 28, xx = i % 28;
        unsigned a = q0u[r*8 + (xx >> 2)];
        unsigned b = q0u[r*8 + (xx >> 2) + 1];
        Wn[i] = __funnelshift_r(a, b, 8*(xx & 3));
    }
    __syncthreads();

    // phase 3: 5x5 window sums
    for (int i = tid; i < 576; i += 384){
        int y = i / 24, xx = i % 24;
        unsigned s = 0;
        #pragma unroll
        for (int ky = 0; ky < 5; ky++){
            s = __dp4a(Wn[(y + ky)*28 + xx], 0x01010101u, s);
            s += (q0u[(y + ky)*8 + ((xx + 4) >> 2)] >> (8*((xx + 4) & 3))) & 0xffu;
        }
        Ps[i] = s;
    }
    __syncthreads();

    // phase 4: main dp4a conv
    if (tid < 360){
        int y = tid / 15, r = tid % 15;
        int xg = r / 5, cg = r % 5;
        int x0 = xg * 8;
        unsigned acc[8][4];
        #pragma unroll
        for (int xx = 0; xx < 8; xx++)
            #pragma unroll
            for (int c = 0; c < 4; c++) acc[xx][c] = 0u;

        #pragma unroll
        for (int ky = 0; ky < 5; ky++){
            const uint4* w4 = (const uint4*)&Wn[(y + ky)*28 + x0];
            uint4 a0 = w4[0], a1 = w4[1], a2 = w4[2];
            unsigned win[12] = {a0.x,a0.y,a0.z,a0.w, a1.x,a1.y,a1.z,a1.w, a2.x,a2.y,a2.z,a2.w};
            uint4 wlo = *(const uint4*)&wlo_s[ky*20 + cg*4];
            uint4 whi = *(const uint4*)&whi_s[ky*20 + cg*4];
            #pragma unroll
            for (int xx = 0; xx < 8; xx++){
                acc[xx][0] = __dp4a(win[xx], wlo.x, acc[xx][0]);
                acc[xx][1] = __dp4a(win[xx], wlo.y, acc[xx][1]);
                acc[xx][2] = __dp4a(win[xx], wlo.z, acc[xx][2]);
                acc[xx][3] = __dp4a(win[xx], wlo.w, acc[xx][3]);
                acc[xx][0] = __dp4a(win[xx+4], whi.x, acc[xx][0]);
                acc[xx][1] = __dp4a(win[xx+4], whi.y, acc[xx][1]);
                acc[xx][2] = __dp4a(win[xx+4], whi.z, acc[xx][2]);
                acc[xx][3] = __dp4a(win[xx+4], whi.w, acc[xx][3]);
            }
        }

        float s_w, z_w; get_sz(0, s_w, z_w);
        float f1 = S1 * s_w;
        float f2 = f1 * z_w;
        float Pv[8];
        #pragma unroll
        for (int xx = 0; xx < 8; xx++) Pv[xx] = (float)Ps[y*24 + x0 + xx];

        #pragma unroll
        for (int c = 0; c < 4; c++){
            int ch = cg*4 + c;
            float Cc = cc_s[ch];
            #pragma unroll
            for (int xx = 0; xx < 8; xx++){
                float val = f1 * (float)(int)acc[xx][c] - f2 * Pv[xx] + Cc;
                float v = rintf(fmaxf(val * INV_S2, 0.0f));
                q1[ch*576 + y*24 + x0 + xx] = (unsigned char)(unsigned)v;
            }
        }
    }
    __syncthreads();

    // phase 5: pool 2x2 -> channel-packed g_act1
    for (int i = tid; i < 2880; i += 384){
        int c = i / 144, rr = (i % 144) / 12, cc = i % 12;
        const unsigned char* b0 = q1 + c*576 + (2*rr)*24 + 2*cc;
        unsigned char m = max(max(b0[0], b0[1]), max(b0[24], b0[25]));
        g_act1[((img*12 + rr)*5 + (c >> 2))*48 + cc*4 + (c & 3)] = m;
    }
}

// ---------------- conv2 via dp4a + quant + pool ----------------
#define S2C (6.0f/255.0f)
__global__ void __launch_bounds__(256) conv2_kernel(){
    __shared__ unsigned Wq_s[5*25*C2_CPAD];
    __shared__ unsigned Xs[2*12*5*12];
    __shared__ unsigned Sw[2*8*8];
    __shared__ unsigned char q2[2*C2_CPAD*64];

    int tid = threadIdx.x;
    int imgbase = blockIdx.x * 2;

    for (int i = tid; i < 1625; i += 256)
        ((uint4*)Wq_s)[i] = ((const uint4*)g_w2q)[i];
    {
        const uint4* xsrc = (const uint4*)(g_act1 + imgbase*2880);
        for (int i = tid; i < 360; i += 256) ((uint4*)Xs)[i] = xsrc[i];
    }
    __syncthreads();

    if (tid < 128){
        int li = tid / 64, t = tid % 64;
        int oy = t / 8, ox = t % 8;
        unsigned s = 0;
        for (int ky = 0; ky < 5; ky++)
            for (int p = 0; p < 5; p++){
                const unsigned* row = &Xs[((li*12 + oy + ky)*5 + p)*12];
                #pragma unroll
                for (int kx = 0; kx < 5; kx++)
                    s = __dp4a(row[ox + kx], 0x01010101u, s);
            }
        Sw[li*64 + oy*8 + ox] = s;
    }

    int active = tid < 208;
    int li = 0, y = 0, cg = 0;
    unsigned acc[8][4];
    #pragma unroll
    for (int xx = 0; xx < 8; xx++)
        #pragma unroll
        for (int c = 0; c < 4; c++) acc[xx][c] = 0u;

    if (active){
        li = tid / 104;
        int t = tid % 104;
        y = t / 13; cg = t % 13;

        #pragma unroll 1
        for (int p = 0; p < 5; p++){
            #pragma unroll
            for (int ky = 0; ky < 5; ky++){
                const uint4* xr4 = (const uint4*)&Xs[((li*12 + y + ky)*5 + p)*12];
                uint4 a0 = xr4[0], a1 = xr4[1], a2 = xr4[2];
                unsigned xv[12] = {a0.x,a0.y,a0.z,a0.w, a1.x,a1.y,a1.z,a1.w, a2.x,a2.y,a2.z,a2.w};
                #pragma unroll
                for (int kx = 0; kx < 5; kx++){
                    uint4 w = *(const uint4*)&Wq_s[(p*25 + ky*5 + kx)*C2_CPAD + cg*4];
                    #pragma unroll
                    for (int xx = 0; xx < 8; xx++){
                        unsigned xvv = xv[xx + kx];
                        acc[xx][0] = __dp4a(xvv, w.x, acc[xx][0]);
                        acc[xx][1] = __dp4a(xvv, w.y, acc[xx][1]);
                        acc[xx][2] = __dp4a(xvv, w.z, acc[xx][2]);
                        acc[xx][3] = __dp4a(xvv, w.w, acc[xx][3]);
                    }
                }
            }
        }
    }
    __syncthreads();

    if (active){
        float s2w, z2w; get_sz(2, s2w, z2w);
        float S2s = S2C * s2w;
        int zp2 = (int)z2w;
        #pragma unroll
        for (int c = 0; c < 4; c++){
            int ch = cg*4 + c;
            float beff = g_b2eff[ch];
            #pragma unroll
            for (int xx = 0; xx < 8; xx++){
                int idiff = (int)acc[xx][c] - zp2 * (int)Sw[li*64 + y*8 + xx];
                float val = S2s * (float)idiff + beff;
                float v = rintf(fmaxf(val * INV_S3, 0.0f));
                q2[((li*C2_CPAD + ch)*8 + y)*8 + xx] = (unsigned char)(unsigned)v;
            }
        }
    }
    __syncthreads();

    for (int i = tid; i < 1600; i += 256){
        int im = i / 800, rest = i % 800;
        int ch = rest / 16, pr = (rest % 16) / 4, pc = rest % 4;
        const unsigned char* bp = q2 + ((im*C2_CPAD + ch)*8 + 2*pr)*8 + 2*pc;
        unsigned char m = max(max(bp[0], bp[1]), max(bp[8], bp[9]));
        g_act2[((imgbase + im)*50 + ch)*16 + pr*4 + pc] = m;
    }
}

// ---------------- rowsum of act2 ----------------
__global__ void __launch_bounds__(256) rowsum_kernel(){
    int warp = threadIdx.x / 32, lane = threadIdx.x % 32;
    int row = blockIdx.x*8 + warp;
    const unsigned* xr = (const unsigned*)(g_act2) + row*200;
    unsigned s = 0;
    for (int k = lane; k < 200; k += 32) s = __dp4a(xr[k], 0x01010101u, s);
    #pragma unroll
    for (int off = 16; off; off >>= 1) s += __shfl_down_sync(0xffffffffu, s, off);
    if (lane == 0) g_rowsum[row] = (int)s;
}

// ---------------- fc1 via dp4a GEMM + quant + dequant ----------------
#define S3C (8.0f/255.0f)
__global__ void __launch_bounds__(256) fc1_kernel(){
    __shared__ unsigned Xt[8][68];
    __shared__ unsigned Wt[8][68];
    int tid = threadIdx.x;
    int m0 = blockIdx.x * 64, n0 = blockIdx.y * 64;
    int tx = tid % 16, ty = tid / 16;
    unsigned acc[4][4] = {};

    const unsigned* Xg = (const unsigned*)g_act2;

    #pragma unroll 1
    for (int kt = 0; kt < 25; kt++){
        int kp0 = kt * 8;
        {
            int r = tid / 4, seg = tid % 4;
            uint2 u = *(const uint2*)&Xg[(m0 + r)*200 + kp0 + seg*2];
            Xt[seg*2][r]     = u.x;
            Xt[seg*2 + 1][r] = u.y;
        }
        if (tid < 128){
            int kr = tid / 16, nc = tid % 16;
            *(uint4*)&Wt[kr][nc*4] = *(const uint4*)&g_fc1q[(kp0 + kr)*512 + n0 + nc*4];
        }
        __syncthreads();

        #pragma unroll
        for (int kk = 0; kk < 8; kk++){
            uint4 a = *(uint4*)&Xt[kk][ty*4];
            uint4 b = *(uint4*)&Wt[kk][tx*4];
            acc[0][0]=__dp4a(a.x,b.x,acc[0][0]); acc[0][1]=__dp4a(a.x,b.y,acc[0][1]); acc[0][2]=__dp4a(a.x,b.z,acc[0][2]); acc[0][3]=__dp4a(a.x,b.w,acc[0][3]);
            acc[1][0]=__dp4a(a.y,b.x,acc[1][0]); acc[1][1]=__dp4a(a.y,b.y,acc[1][1]); acc[1][2]=__dp4a(a.y,b.z,acc[1][2]); acc[1][3]=__dp4a(a.y,b.w,acc[1][3]);
            acc[2][0]=__dp4a(a.z,b.x,acc[2][0]); acc[2][1]=__dp4a(a.z,b.y,acc[2][1]); acc[2][2]=__dp4a(a.z,b.z,acc[2][2]); acc[2][3]=__dp4a(a.z,b.w,acc[2][3]);
            acc[3][0]=__dp4a(a.w,b.x,acc[3][0]); acc[3][1]=__dp4a(a.w,b.y,acc[3][1]); acc[3][2]=__dp4a(a.w,b.z,acc[3][2]); acc[3][3]=__dp4a(a.w,b.w,acc[3][3]);
        }
        __syncthreads();
    }

    float s3w, z3w; get_sz(4, s3w, z3w);
    float S3s = S3C * s3w;
    int zp3 = (int)z3w;

    #pragma unroll
    for (int i = 0; i < 4; i++){
        int m = m0 + ty*4 + i;
        int rs = g_rowsum[m];
        #pragma unroll
        for (int j = 0; j < 4; j++){
            int n = n0 + tx*4 + j;
            if (n < 500){
                float yv = S3s * (float)((int)acc[i][j] - zp3 * rs) + g_b3eff[n];
                float v = rintf(fmaxf(yv * INV_S4, 0.0f));
                g_xf[m*500 + n] = S4 * (float)((unsigned)v & 0xffu);
            }
        }
    }
}

// ---------------- fc2 + log_softmax ----------------
__global__ void __launch_bounds__(128) fc2_kernel(const float* __restrict__ w,
                                                  const float* __restrict__ bias,
                                                  float* __restrict__ out){
    __shared__ float ws[5000];
    __shared__ float bsh[10];
    int tid = threadIdx.x;
    for (int i = tid; i < 5000; i += 128){
        int j = i / 500, k = i % 500;
        ws[k*10 + j] = w[i];
    }
    if (tid < 10) bsh[tid] = bias[tid];
    __syncthreads();

    int warp = tid / 32, lane = tid % 32;
    int row = blockIdx.x*4 + warp;
    float acc[10];
    #pragma unroll
    for (int j = 0; j < 10; j++) acc[j] = 0.0f;

    for (int k = lane; k < 500; k += 32){
        float xv = g_xf[row*500 + k];
        const float* wr = ws + k*10;
        #pragma unroll
        for (int j = 0; j < 10; j++) acc[j] += xv * wr[j];
    }
    #pragma unroll
    for (int j = 0; j < 10; j++){
        #pragma unroll
        for (int off = 16; off; off >>= 1)
            acc[j] += __shfl_down_sync(0xffffffffu, acc[j], off);
    }
    if (lane == 0){
        float l[10], m = -1e30f;
        #pragma unroll
        for (int j = 0; j < 10; j++){ l[j] = acc[j] + bsh[j]; m = fmaxf(m, l[j]); }
        float s = 0.0f;
        #pragma unroll
        for (int j = 0; j < 10; j++) s += expf(l[j] - m);
        float ls = logf(s);
        #pragma unroll
        for (int j = 0; j < 10; j++) out[row*10 + j] = l[j] - m - ls;
    }
}

// ---------------- launch ----------------
extern "C" void kernel_launch(void* const* d_in, const int* in_sizes, int n_in,
                              void* d_out, int out_size){
    const float* x   = (const float*)d_in[0];
    const float* c1w = (const float*)d_in[1];
    const float* c1b = (const float*)d_in[2];
    const float* c2w = (const float*)d_in[3];
    const float* c2b = (const float*)d_in[4];
    const float* f1w = (const float*)d_in[5];
    const float* f1b = (const float*)d_in[6];
    const float* f2w = (const float*)d_in[7];
    const float* f2b = (const float*)d_in[8];

    init_mm_kernel<<<1, 32>>>();
    minmax_kernel<<<72, 256>>>(c1w, c1b, c2w, c2b, f1w, f1b);
    effs_kernel<<<429, 256>>>(c1w, c1b, c2w, c2b, f1w, f1b);
    conv1_kernel<<<BATCH, 384>>>(x);
    conv2_kernel<<<BATCH/2, 256>>>();
    rowsum_kernel<<<BATCH/8, 256>>>();
    fc1_kernel<<<dim3(BATCH/64, 8), 256>>>();
    fc2_kernel<<<BATCH/4, 128>>>(f2w, f2b, (float*)d_out);
}

// round 5
// speedup vs baseline: 2.4135x; 1.0680x over previous
#include <cuda_runtime.h>
#include <cstdint>

// ---------------- constants (STATS are fixed) ----------------
#define S1 (3.5f/255.0f)   // conv1 stat (-0.5, 3.0)
#define ZP1 36.0f          // trunc(0.5/S1)
#define INV_S2 42.5f       // 255/6  (exact)
#define INV_S3 31.875f     // 255/8  (exact)
#define INV_S4 25.5f       // 255/10 (exact)
#define S4 (10.0f/255.0f)
#define S2C (6.0f/255.0f)
#define S3C (8.0f/255.0f)

#define BATCH 4096
#define C2_CPAD 52

// ---------------- device scratch ----------------
__device__ unsigned g_mmkey[12];
__device__ __align__(16) unsigned g_w1lo[5*20];
__device__ __align__(16) unsigned g_w1hi[5*20];
__device__ float g_c1c[20];
__device__ __align__(16) unsigned g_w2q[5*25*C2_CPAD];  // conv2 wq packed: [p][r=ky*5+kx][c]
__device__ float g_b2eff[C2_CPAD];
__device__ __align__(16) unsigned g_fc1q[200*512];
__device__ float g_b3eff[512];
__device__ __align__(16) unsigned char g_act1[BATCH*12*5*12*4];
__device__ __align__(16) unsigned char g_act2[BATCH*50*4*4];
__device__ int g_rowsum[BATCH];
__device__ float g_xf[BATCH*500];

// ---------------- helpers ----------------
__device__ __forceinline__ float clip255(float v){ return fminf(fmaxf(v, 0.0f), 255.0f); }
__device__ __forceinline__ unsigned f2key(float f){
    unsigned u = __float_as_uint(f);
    return (u & 0x80000000u) ? ~u : (u | 0x80000000u);
}
__device__ __forceinline__ float key2f(unsigned k){
    return __uint_as_float((k & 0x80000000u) ? (k & 0x7fffffffu) : ~k);
}
__device__ __forceinline__ void get_sz(int t, float& scale, float& zp){
    float mn = key2f(g_mmkey[2*t]);
    float mx = key2f(g_mmkey[2*t+1]);
    scale = (mx - mn) / 255.0f;
    zp = truncf(clip255(-mn / scale));
}
__device__ __forceinline__ float qround(float v, float scale, float zp){
    return rintf(clip255(zp + v / scale));
}

// ---------------- init min/max ----------------
__global__ void init_mm_kernel(){
    int t = threadIdx.x;
    if (t < 6){ g_mmkey[2*t] = 0xFFFFFFFFu; g_mmkey[2*t+1] = 0u; }
}

// ---------------- min/max over 6 param tensors ----------------
__global__ void minmax_kernel(const float* __restrict__ c1w, const float* __restrict__ c1b,
                              const float* __restrict__ c2w, const float* __restrict__ c2b,
                              const float* __restrict__ f1w, const float* __restrict__ f1b){
    __shared__ unsigned smn[256], smx[256];
    int b = blockIdx.x, tid = threadIdx.x;
    const float* p; int n, t, sub, nb;
    if (b < 64)      { t = 4; p = f1w; n = 400000; sub = b;      nb = 64; }
    else if (b < 68) { t = 2; p = c2w; n = 25000;  sub = b - 64; nb = 4;  }
    else if (b == 68){ t = 0; p = c1w; n = 500;    sub = 0;      nb = 1;  }
    else if (b == 69){ t = 1; p = c1b; n = 20;     sub = 0;      nb = 1;  }
    else if (b == 70){ t = 3; p = c2b; n = 50;     sub = 0;      nb = 1;  }
    else             { t = 5; p = f1b; n = 500;    sub = 0;      nb = 1;  }

    unsigned lmin = 0xFFFFFFFFu, lmax = 0u;
    for (int i = sub*256 + tid; i < n; i += nb*256){
        unsigned k = f2key(p[i]);
        lmin = min(lmin, k); lmax = max(lmax, k);
    }
    smn[tid] = lmin; smx[tid] = lmax;
    __syncthreads();
    for (int s = 128; s; s >>= 1){
        if (tid < s){
            smn[tid] = min(smn[tid], smn[tid+s]);
            smx[tid] = max(smx[tid], smx[tid+s]);
        }
        __syncthreads();
    }
    if (tid == 0){
        atomicMin(&g_mmkey[2*t],   smn[0]);
        atomicMax(&g_mmkey[2*t+1], smx[0]);
    }
}

// ---------------- build packed weights / constants ----------------
__global__ void effs_kernel(const float* __restrict__ c1w, const float* __restrict__ c1b,
                            const float* __restrict__ c2w, const float* __restrict__ c2b,
                            const float* __restrict__ f1w, const float* __restrict__ f1b){
    int idx = blockIdx.x*blockDim.x + threadIdx.x;
    if (idx < 100){
        int ky = idx / 20, ch = idx % 20;
        float s, z; get_sz(0, s, z);
        unsigned lo = 0u;
        #pragma unroll
        for (int j = 0; j < 4; j++){
            unsigned wq = (unsigned)qround(c1w[ch*25 + ky*5 + j], s, z);
            lo |= (wq & 0xffu) << (8*j);
        }
        g_w1lo[idx] = lo;
        g_w1hi[idx] = (unsigned)qround(c1w[ch*25 + ky*5 + 4], s, z) & 0xffu;
    } else if (idx < 120){
        int ch = idx - 100;
        float s, z; get_sz(0, s, z);
        float wsum = 0.0f;
        for (int k = 0; k < 25; k++) wsum += qround(c1w[ch*25 + k], s, z);
        float sb, zb; get_sz(1, sb, zb);
        float beff = sb * (qround(c1b[ch], sb, zb) + zb);
        g_c1c[ch] = beff + (S1 * s) * (900.0f * z - 36.0f * wsum);
    } else if (idx < 6620){                               // conv2 wq packed [p][r][c]
        int e = idx - 120;
        int p = e / (25*C2_CPAD), r = (e / C2_CPAD) % 25, c = e % C2_CPAD;
        unsigned pk = 0u;
        if (c < 50){
            float s, z; get_sz(2, s, z);
            #pragma unroll
            for (int j = 0; j < 4; j++){
                int ci = p*4 + j;
                unsigned wq = (unsigned)qround(c2w[c*500 + ci*25 + r], s, z);
                pk |= (wq & 0xffu) << (8*j);
            }
        }
        g_w2q[e] = pk;
    } else if (idx < 6672){
        int c = idx - 6620;
        float val = 0.0f;
        if (c < 50){
            float s, z; get_sz(3, s, z);
            val = s * (qround(c2b[c], s, z) + z);
        }
        g_b2eff[c] = val;
    } else if (idx < 109072){
        int e = idx - 6672;
        int kp = e / 512, n = e % 512;
        unsigned pk = 0u;
        if (n < 500){
            float s, z; get_sz(4, s, z);
            #pragma unroll
            for (int j = 0; j < 4; j++){
                int k = kp*4 + j;
                unsigned wq = (unsigned)qround(f1w[n*800 + k], s, z);
                pk |= (wq & 0xffu) << (8*j);
            }
        }
        g_fc1q[e] = pk;
    } else if (idx < 109584){
        int n = idx - 109072;
        float val = 0.0f;
        if (n < 500){
            float s, z; get_sz(5, s, z);
            val = s * (qround(f1b[n], s, z) + z);
        }
        g_b3eff[n] = val;
    }
}

// ---------------- conv1 via dp4a + quant + pool ----------------
__global__ void __launch_bounds__(384) conv1_kernel(const float* __restrict__ x){
    __shared__ unsigned q0u[28*8];
    __shared__ unsigned Wn[28*28];
    __shared__ unsigned Ps[24*24];
    __shared__ unsigned wlo_s[100], whi_s[100];
    __shared__ float cc_s[20];
    __shared__ unsigned char q1[20*24*24];

    int img = blockIdx.x, tid = threadIdx.x;
    const float* xi = x + img*784;

    if (tid < 224){
        int r = tid / 8, c4 = tid % 8;
        unsigned pk = 0u;
        if (c4 < 7){
            #pragma unroll
            for (int j = 0; j < 4; j++){
                float v = xi[r*28 + c4*4 + j];
                unsigned q = (unsigned)rintf(clip255(ZP1 + v / S1));
                pk |= (q & 0xffu) << (8*j);
            }
        }
        q0u[r*8 + c4] = pk;
    }
    for (int i = tid; i < 100; i += 384){ wlo_s[i] = g_w1lo[i]; whi_s[i] = g_w1hi[i]; }
    if (tid < 20) cc_s[tid] = g_c1c[tid];
    __syncthreads();

    for (int i = tid; i < 784; i += 384){
        int r = i / 28, xx = i % 28;
        unsigned a = q0u[r*8 + (xx >> 2)];
        unsigned b = q0u[r*8 + (xx >> 2) + 1];
        Wn[i] = __funnelshift_r(a, b, 8*(xx & 3));
    }
    __syncthreads();

    for (int i = tid; i < 576; i += 384){
        int y = i / 24, xx = i % 24;
        unsigned s = 0;
        #pragma unroll
        for (int ky = 0; ky < 5; ky++){
            s = __dp4a(Wn[(y + ky)*28 + xx], 0x01010101u, s);
            s += (q0u[(y + ky)*8 + ((xx + 4) >> 2)] >> (8*((xx + 4) & 3))) & 0xffu;
        }
        Ps[i] = s;
    }
    __syncthreads();

    if (tid < 360){
        int y = tid / 15, r = tid % 15;
        int xg = r / 5, cg = r % 5;
        int x0 = xg * 8;
        unsigned acc[8][4];
        #pragma unroll
        for (int xx = 0; xx < 8; xx++)
            #pragma unroll
            for (int c = 0; c < 4; c++) acc[xx][c] = 0u;

        #pragma unroll
        for (int ky = 0; ky < 5; ky++){
            const uint4* w4 = (const uint4*)&Wn[(y + ky)*28 + x0];
            uint4 a0 = w4[0], a1 = w4[1], a2 = w4[2];
            unsigned win[12] = {a0.x,a0.y,a0.z,a0.w, a1.x,a1.y,a1.z,a1.w, a2.x,a2.y,a2.z,a2.w};
            uint4 wlo = *(const uint4*)&wlo_s[ky*20 + cg*4];
            uint4 whi = *(const uint4*)&whi_s[ky*20 + cg*4];
            #pragma unroll
            for (int xx = 0; xx < 8; xx++){
                acc[xx][0] = __dp4a(win[xx], wlo.x, acc[xx][0]);
                acc[xx][1] = __dp4a(win[xx], wlo.y, acc[xx][1]);
                acc[xx][2] = __dp4a(win[xx], wlo.z, acc[xx][2]);
                acc[xx][3] = __dp4a(win[xx], wlo.w, acc[xx][3]);
                acc[xx][0] = __dp4a(win[xx+4], whi.x, acc[xx][0]);
                acc[xx][1] = __dp4a(win[xx+4], whi.y, acc[xx][1]);
                acc[xx][2] = __dp4a(win[xx+4], whi.z, acc[xx][2]);
                acc[xx][3] = __dp4a(win[xx+4], whi.w, acc[xx][3]);
            }
        }

        float s_w, z_w; get_sz(0, s_w, z_w);
        float f1 = S1 * s_w;
        float f2 = f1 * z_w;
        float Pv[8];
        #pragma unroll
        for (int xx = 0; xx < 8; xx++) Pv[xx] = (float)Ps[y*24 + x0 + xx];

        #pragma unroll
        for (int c = 0; c < 4; c++){
            int ch = cg*4 + c;
            float Cc = cc_s[ch];
            #pragma unroll
            for (int xx = 0; xx < 8; xx++){
                float val = f1 * (float)(int)acc[xx][c] - f2 * Pv[xx] + Cc;
                float v = rintf(fmaxf(val * INV_S2, 0.0f));
                q1[ch*576 + y*24 + x0 + xx] = (unsigned char)(unsigned)v;
            }
        }
    }
    __syncthreads();

    for (int i = tid; i < 2880; i += 384){
        int c = i / 144, rr = (i % 144) / 12, cc = i % 12;
        const unsigned char* b0 = q1 + c*576 + (2*rr)*24 + 2*cc;
        unsigned char m = max(max(b0[0], b0[1]), max(b0[24], b0[25]));
        g_act1[((img*12 + rr)*5 + (c >> 2))*48 + cc*4 + (c & 3)] = m;
    }
}

// ---------------- conv2 via int8 tensor-core mma + quant + pool ----------------
// block = 2 images, 256 threads = 8 warps.
// GEMM per image: M=64 (positions), N=52(pad 56), K=500(pad 512).
// k-order: k = (r*5 + p)*4 + j, r=ky*5+kx, p=ci/4, j=ci%4.
// A fragment u32 == channel-packed act1 word; B fragment u32 == g_w2q word.
__global__ void __launch_bounds__(256) conv2_kernel(){
    __shared__ unsigned Xs[2*12*5*12];       // [li][y][p][x]
    __shared__ unsigned Bs[128*56];          // [g][n], zero-padded rows/cols
    __shared__ int offA[128];
    __shared__ unsigned Sw[2*8*8];
    __shared__ float beff_s[C2_CPAD];
    __shared__ unsigned char q2[2*C2_CPAD*64];

    int tid = threadIdx.x;
    int imgbase = blockIdx.x * 2;

    // load act1 tiles
    {
        const uint4* xsrc = (const uint4*)(g_act1 + imgbase*2880);
        for (int i = tid; i < 360; i += 256) ((uint4*)Xs)[i] = xsrc[i];
    }
    // fill B smem [g][56]: g<125 from g_w2q (row (p*25+r), 13 uint4), else zero
    for (int i = tid; i < 128*14; i += 256){
        int g = i / 14, c4 = i % 14;
        uint4 v = make_uint4(0u,0u,0u,0u);
        if (g < 125 && c4 < 13){
            int r = g / 5, p = g % 5;
            v = *(const uint4*)&g_w2q[(p*25 + r)*C2_CPAD + c4*4];
        }
        ((uint4*)Bs)[g*14 + c4] = v;
    }
    if (tid < 128){
        int g = tid;
        int r = (g < 125) ? g/5 : 0, p = (g < 125) ? g%5 : 0;
        int ky = r/5, kx = r%5;
        offA[tid] = ky*60 + p*12 + kx;
    }
    if (tid < C2_CPAD) beff_s[tid] = g_b2eff[tid];
    __syncthreads();

    // window sums (for zp correction)
    if (tid < 128){
        int li = tid / 64, t = tid % 64;
        int oy = t / 8, ox = t % 8;
        unsigned s = 0;
        for (int ky = 0; ky < 5; ky++)
            for (int p = 0; p < 5; p++){
                const unsigned* row = &Xs[((li*12 + oy + ky)*5 + p)*12];
                #pragma unroll
                for (int kx = 0; kx < 5; kx++)
                    s = __dp4a(row[ox + kx], 0x01010101u, s);
            }
        Sw[li*64 + oy*8 + ox] = s;
    }

    // mma main: warp -> (li, mtile); rows m = mtile*16 + lr (+8)
    int w = tid >> 5, l = tid & 31;
    int li = w >> 2, mtile = w & 3;
    int lr = l >> 2, lc = l & 3;
    int oy0 = mtile*2;
    int base0 = li*720 + oy0*60 + lr;
    int base1 = base0 + 60;

    int acc[7][4];
    #pragma unroll
    for (int t = 0; t < 7; t++)
        #pragma unroll
        for (int j = 0; j < 4; j++) acc[t][j] = 0;

    #pragma unroll 1
    for (int step = 0; step < 16; step++){
        int g0 = step*8 + lc;
        int g1 = g0 + 4;
        unsigned a0 = Xs[base0 + offA[g0]];
        unsigned a1 = Xs[base1 + offA[g0]];
        unsigned a2 = Xs[base0 + offA[g1]];   // if g1 pad, B row is 0 -> contributes 0
        unsigned a3 = Xs[base1 + offA[g1]];
        const unsigned* b0r = &Bs[g0*56 + lr];
        const unsigned* b1r = &Bs[g1*56 + lr];
        #pragma unroll
        for (int t = 0; t < 7; t++){
            unsigned b0 = b0r[t*8];
            unsigned b1 = b1r[t*8];
            asm volatile(
                "mma.sync.aligned.m16n8k32.row.col.s32.u8.u8.s32 "
                "{%0,%1,%2,%3}, {%4,%5,%6,%7}, {%8,%9}, {%0,%1,%2,%3};"
                : "+r"(acc[t][0]), "+r"(acc[t][1]), "+r"(acc[t][2]), "+r"(acc[t][3])
                : "r"(a0), "r"(a1), "r"(a2), "r"(a3), "r"(b0), "r"(b1));
        }
    }
    __syncthreads();   // Sw + all smem writes visible

    // epilogue: quant + store q2
    {
        float s2w, z2w; get_sz(2, s2w, z2w);
        float S2s = S2C * s2w;
        int zp2 = (int)z2w;
        #pragma unroll
        for (int half = 0; half < 2; half++){
            int oy = oy0 + half, ox = lr;
            int sw = (int)Sw[li*64 + oy*8 + ox];
            #pragma unroll
            for (int t = 0; t < 7; t++){
                #pragma unroll
                for (int j = 0; j < 2; j++){
                    int ch = t*8 + lc*2 + j;
                    if (ch < C2_CPAD){
                        int cval = acc[t][half*2 + j];
                        float val = S2s * (float)(cval - zp2*sw) + beff_s[ch];
                        float v = rintf(fmaxf(val * INV_S3, 0.0f));
                        q2[((li*C2_CPAD + ch)*8 + oy)*8 + ox] = (unsigned char)(unsigned)v;
                    }
                }
            }
        }
    }
    __syncthreads();

    // pool 2x2 -> g_act2
    for (int i = tid; i < 1600; i += 256){
        int im = i / 800, rest = i % 800;
        int ch = rest / 16, pr = (rest % 16) / 4, pc = rest % 4;
        const unsigned char* bp = q2 + ((im*C2_CPAD + ch)*8 + 2*pr)*8 + 2*pc;
        unsigned char m = max(max(bp[0], bp[1]), max(bp[8], bp[9]));
        g_act2[((imgbase + im)*50 + ch)*16 + pr*4 + pc] = m;
    }
}

// ---------------- rowsum of act2 ----------------
__global__ void __launch_bounds__(256) rowsum_kernel(){
    int warp = threadIdx.x / 32, lane = threadIdx.x % 32;
    int row = blockIdx.x*8 + warp;
    const unsigned* xr = (const unsigned*)(g_act2) + row*200;
    unsigned s = 0;
    for (int k = lane; k < 200; k += 32) s = __dp4a(xr[k], 0x01010101u, s);
    #pragma unroll
    for (int off = 16; off; off >>= 1) s += __shfl_down_sync(0xffffffffu, s, off);
    if (lane == 0) g_rowsum[row] = (int)s;
}

// ---------------- fc1 via dp4a GEMM + quant + dequant ----------------
__global__ void __launch_bounds__(256) fc1_kernel(){
    __shared__ unsigned Xt[8][68];
    __shared__ unsigned Wt[8][68];
    int tid = threadIdx.x;
    int m0 = blockIdx.x * 64, n0 = blockIdx.y * 64;
    int tx = tid % 16, ty = tid / 16;
    unsigned acc[4][4] = {};

    const unsigned* Xg = (const unsigned*)g_act2;

    #pragma unroll 1
    for (int kt = 0; kt < 25; kt++){
        int kp0 = kt * 8;
        {
            int r = tid / 4, seg = tid % 4;
            uint2 u = *(const uint2*)&Xg[(m0 + r)*200 + kp0 + seg*2];
            Xt[seg*2][r]     = u.x;
            Xt[seg*2 + 1][r] = u.y;
        }
        if (tid < 128){
            int kr = tid / 16, nc = tid % 16;
            *(uint4*)&Wt[kr][nc*4] = *(const uint4*)&g_fc1q[(kp0 + kr)*512 + n0 + nc*4];
        }
        __syncthreads();

        #pragma unroll
        for (int kk = 0; kk < 8; kk++){
            uint4 a = *(uint4*)&Xt[kk][ty*4];
            uint4 b = *(uint4*)&Wt[kk][tx*4];
            acc[0][0]=__dp4a(a.x,b.x,acc[0][0]); acc[0][1]=__dp4a(a.x,b.y,acc[0][1]); acc[0][2]=__dp4a(a.x,b.z,acc[0][2]); acc[0][3]=__dp4a(a.x,b.w,acc[0][3]);
            acc[1][0]=__dp4a(a.y,b.x,acc[1][0]); acc[1][1]=__dp4a(a.y,b.y,acc[1][1]); acc[1][2]=__dp4a(a.y,b.z,acc[1][2]); acc[1][3]=__dp4a(a.y,b.w,acc[1][3]);
            acc[2][0]=__dp4a(a.z,b.x,acc[2][0]); acc[2][1]=__dp4a(a.z,b.y,acc[2][1]); acc[2][2]=__dp4a(a.z,b.z,acc[2][2]); acc[2][3]=__dp4a(a.z,b.w,acc[2][3]);
            acc[3][0]=__dp4a(a.w,b.x,acc[3][0]); acc[3][1]=__dp4a(a.w,b.y,acc[3][1]); acc[3][2]=__dp4a(a.w,b.z,acc[3][2]); acc[3][3]=__dp4a(a.w,b.w,acc[3][3]);
        }
        __syncthreads();
    }

    float s3w, z3w; get_sz(4, s3w, z3w);
    float S3s = S3C * s3w;
    int zp3 = (int)z3w;

    #pragma unroll
    for (int i = 0; i < 4; i++){
        int m = m0 + ty*4 + i;
        int rs = g_rowsum[m];
        #pragma unroll
        for (int j = 0; j < 4; j++){
            int n = n0 + tx*4 + j;
            if (n < 500){
                float yv = S3s * (float)((int)acc[i][j] - zp3 * rs) + g_b3eff[n];
                float v = rintf(fmaxf(yv * INV_S4, 0.0f));
                g_xf[m*500 + n] = S4 * (float)((unsigned)v & 0xffu);
            }
        }
    }
}

// ---------------- fc2 + log_softmax ----------------
__global__ void __launch_bounds__(128) fc2_kernel(const float* __restrict__ w,
                                                  const float* __restrict__ bias,
                                                  float* __restrict__ out){
    __shared__ float ws[5000];
    __shared__ float bsh[10];
    int tid = threadIdx.x;
    for (int i = tid; i < 5000; i += 128){
        int j = i / 500, k = i % 500;
        ws[k*10 + j] = w[i];
    }
    if (tid < 10) bsh[tid] = bias[tid];
    __syncthreads();

    int warp = tid / 32, lane = tid % 32;
    int row = blockIdx.x*4 + warp;
    float acc[10];
    #pragma unroll
    for (int j = 0; j < 10; j++) acc[j] = 0.0f;

    for (int k = lane; k < 500; k += 32){
        float xv = g_xf[row*500 + k];
        const float* wr = ws + k*10;
        #pragma unroll
        for (int j = 0; j < 10; j++) acc[j] += xv * wr[j];
    }
    #pragma unroll
    for (int j = 0; j < 10; j++){
        #pragma unroll
        for (int off = 16; off; off >>= 1)
            acc[j] += __shfl_down_sync(0xffffffffu, acc[j], off);
    }
    if (lane == 0){
        float l[10], m = -1e30f;
        #pragma unroll
        for (int j = 0; j < 10; j++){ l[j] = acc[j] + bsh[j]; m = fmaxf(m, l[j]); }
        float s = 0.0f;
        #pragma unroll
        for (int j = 0; j < 10; j++) s += expf(l[j] - m);
        float ls = logf(s);
        #pragma unroll
        for (int j = 0; j < 10; j++) out[row*10 + j] = l[j] - m - ls;
    }
}

// ---------------- launch ----------------
extern "C" void kernel_launch(void* const* d_in, const int* in_sizes, int n_in,
                              void* d_out, int out_size){
    const float* x   = (const float*)d_in[0];
    const float* c1w = (const float*)d_in[1];
    const float* c1b = (const float*)d_in[2];
    const float* c2w = (const float*)d_in[3];
    const float* c2b = (const float*)d_in[4];
    const float* f1w = (const float*)d_in[5];
    const float* f1b = (const float*)d_in[6];
    const float* f2w = (const float*)d_in[7];
    const float* f2b = (const float*)d_in[8];

    init_mm_kernel<<<1, 32>>>();
    minmax_kernel<<<72, 256>>>(c1w, c1b, c2w, c2b, f1w, f1b);
    effs_kernel<<<429, 256>>>(c1w, c1b, c2w, c2b, f1w, f1b);
    conv1_kernel<<<BATCH, 384>>>(x);
    conv2_kernel<<<BATCH/2, 256>>>();
    rowsum_kernel<<<BATCH/8, 256>>>();
    fc1_kernel<<<dim3(BATCH/64, 8), 256>>>();
    fc2_kernel<<<BATCH/4, 128>>>(f2w, f2b, (float*)d_out);
}

// round 7
// speedup vs baseline: 2.8443x; 1.1785x over previous
#include <cuda_runtime.h>
#include <cstdint>

// ---------------- constants (STATS are fixed) ----------------
#define S1 (3.5f/255.0f)   // conv1 stat (-0.5, 3.0)
#define ZP1 36.0f          // trunc(0.5/S1)
#define INV_S2 42.5f       // 255/6  (exact)
#define INV_S3 31.875f     // 255/8  (exact)
#define INV_S4 25.5f       // 255/10 (exact)
#define S4 (10.0f/255.0f)
#define S2C (6.0f/255.0f)
#define S3C (8.0f/255.0f)

#define BATCH 4096
#define C2_CPAD 52

// ---------------- device scratch ----------------
__device__ unsigned g_mmkey[12];
__device__ __align__(16) unsigned g_w1lo[5*20];
__device__ __align__(16) unsigned g_w1hi[5*20];
__device__ float g_c1c[20];                              // conv1 const, pre-scaled by INV_S2
__device__ __align__(16) unsigned g_w2q[5*25*C2_CPAD];  // conv2 wq packed: [p][r=ky*5+kx][c]
__device__ float g_b2eff[C2_CPAD];
__device__ __align__(16) unsigned g_fc1q[200*512];      // fc1 wq packed: [kp=200][n pad 512]
__device__ float g_b3eff[512];
__device__ __align__(16) unsigned char g_act1[BATCH*12*5*12*4];
__device__ __align__(16) unsigned char g_act2[BATCH*50*4*4];
__device__ int g_rowsum[BATCH];
__device__ float g_xf[BATCH*500];

// ---------------- helpers ----------------
__device__ __forceinline__ float clip255(float v){ return fminf(fmaxf(v, 0.0f), 255.0f); }
__device__ __forceinline__ unsigned f2key(float f){
    unsigned u = __float_as_uint(f);
    return (u & 0x80000000u) ? ~u : (u | 0x80000000u);
}
__device__ __forceinline__ float key2f(unsigned k){
    return __uint_as_float((k & 0x80000000u) ? (k & 0x7fffffffu) : ~k);
}
__device__ __forceinline__ void get_sz(int t, float& scale, float& zp){
    float mn = key2f(g_mmkey[2*t]);
    float mx = key2f(g_mmkey[2*t+1]);
    scale = (mx - mn) / 255.0f;
    zp = truncf(clip255(-mn / scale));
}
__device__ __forceinline__ float qround(float v, float scale, float zp){
    return rintf(clip255(zp + v / scale));
}

// ---------------- init min/max ----------------
__global__ void init_mm_kernel(){
    int t = threadIdx.x;
    if (t < 6){ g_mmkey[2*t] = 0xFFFFFFFFu; g_mmkey[2*t+1] = 0u; }
}

// ---------------- min/max over 6 param tensors ----------------
__global__ void minmax_kernel(const float* __restrict__ c1w, const float* __restrict__ c1b,
                              const float* __restrict__ c2w, const float* __restrict__ c2b,
                              const float* __restrict__ f1w, const float* __restrict__ f1b){
    __shared__ unsigned smn[256], smx[256];
    int b = blockIdx.x, tid = threadIdx.x;
    const float* p; int n, t, sub, nb;
    if (b < 64)      { t = 4; p = f1w; n = 400000; sub = b;      nb = 64; }
    else if (b < 68) { t = 2; p = c2w; n = 25000;  sub = b - 64; nb = 4;  }
    else if (b == 68){ t = 0; p = c1w; n = 500;    sub = 0;      nb = 1;  }
    else if (b == 69){ t = 1; p = c1b; n = 20;     sub = 0;      nb = 1;  }
    else if (b == 70){ t = 3; p = c2b; n = 50;     sub = 0;      nb = 1;  }
    else             { t = 5; p = f1b; n = 500;    sub = 0;      nb = 1;  }

    unsigned lmin = 0xFFFFFFFFu, lmax = 0u;
    for (int i = sub*256 + tid; i < n; i += nb*256){
        unsigned k = f2key(p[i]);
        lmin = min(lmin, k); lmax = max(lmax, k);
    }
    smn[tid] = lmin; smx[tid] = lmax;
    __syncthreads();
    for (int s = 128; s; s >>= 1){
        if (tid < s){
            smn[tid] = min(smn[tid], smn[tid+s]);
            smx[tid] = max(smx[tid], smx[tid+s]);
        }
        __syncthreads();
    }
    if (tid == 0){
        atomicMin(&g_mmkey[2*t],   smn[0]);
        atomicMax(&g_mmkey[2*t+1], smx[0]);
    }
}

// ---------------- build packed weights / constants ----------------
__global__ void effs_kernel(const float* __restrict__ c1w, const float* __restrict__ c1b,
                            const float* __restrict__ c2w, const float* __restrict__ c2b,
                            const float* __restrict__ f1w, const float* __restrict__ f1b){
    int idx = blockIdx.x*blockDim.x + threadIdx.x;
    if (idx < 100){
        int ky = idx / 20, ch = idx % 20;
        float s, z; get_sz(0, s, z);
        unsigned lo = 0u;
        #pragma unroll
        for (int j = 0; j < 4; j++){
            unsigned wq = (unsigned)qround(c1w[ch*25 + ky*5 + j], s, z);
            lo |= (wq & 0xffu) << (8*j);
        }
        g_w1lo[idx] = lo;
        g_w1hi[idx] = (unsigned)qround(c1w[ch*25 + ky*5 + 4], s, z) & 0xffu;
    } else if (idx < 120){
        int ch = idx - 100;
        float s, z; get_sz(0, s, z);
        float wsum = 0.0f;
        for (int k = 0; k < 25; k++) wsum += qround(c1w[ch*25 + k], s, z);
        float sb, zb; get_sz(1, sb, zb);
        float beff = sb * (qround(c1b[ch], sb, zb) + zb);
        g_c1c[ch] = (beff + (S1 * s) * (900.0f * z - 36.0f * wsum)) * INV_S2;
    } else if (idx < 6620){                               // conv2 wq packed [p][r][c]
        int e = idx - 120;
        int p = e / (25*C2_CPAD), r = (e / C2_CPAD) % 25, c = e % C2_CPAD;
        unsigned pk = 0u;
        if (c < 50){
            float s, z; get_sz(2, s, z);
            #pragma unroll
            for (int j = 0; j < 4; j++){
                int ci = p*4 + j;
                unsigned wq = (unsigned)qround(c2w[c*500 + ci*25 + r], s, z);
                pk |= (wq & 0xffu) << (8*j);
            }
        }
        g_w2q[e] = pk;
    } else if (idx < 6672){
        int c = idx - 6620;
        float val = 0.0f;
        if (c < 50){
            float s, z; get_sz(3, s, z);
            val = s * (qround(c2b[c], s, z) + z);
        }
        g_b2eff[c] = val;
    } else if (idx < 109072){
        int e = idx - 6672;
        int kp = e / 512, n = e % 512;
        unsigned pk = 0u;
        if (n < 500){
            float s, z; get_sz(4, s, z);
            #pragma unroll
            for (int j = 0; j < 4; j++){
                int k = kp*4 + j;
                unsigned wq = (unsigned)qround(f1w[n*800 + k], s, z);
                pk |= (wq & 0xffu) << (8*j);
            }
        }
        g_fc1q[e] = pk;
    } else if (idx < 109584){
        int n = idx - 109072;
        float val = 0.0f;
        if (n < 500){
            float s, z; get_sz(5, s, z);
            val = s * (qround(f1b[n], s, z) + z);
        }
        g_b3eff[n] = val;
    }
}

// ---------------- conv1 via dp4a, fused quant+pool (pool-before-round) ----------------
// one image per block, 384 threads, 360 compute: thread -> (rr 0..11, cg 0..4, xp 0..5)
// computes 2 conv rows x 4 conv cols x 4 ch, pools 2x2 on pre-quant floats (monotone), writes 2 u32.
__global__ void __launch_bounds__(384, 3) conv1_kernel(const float* __restrict__ x){
    __shared__ unsigned q0u[28*8];        // q0 bytes, 8 u32 per row (last = pad 0)
    __shared__ unsigned Wn[28*28];        // sliding 4-byte windows per row
    __shared__ unsigned Ps[24*24];        // 5x5 window sums of q0
    __shared__ unsigned wlo_s[100], whi_s[100];
    __shared__ float cc_s[20];

    int img = blockIdx.x, tid = threadIdx.x;
    const float* xi = x + img*784;

    // phase 1: quantize input to u8, packed u32
    if (tid < 224){
        int r = tid / 8, c4 = tid % 8;
        unsigned pk = 0u;
        if (c4 < 7){
            #pragma unroll
            for (int j = 0; j < 4; j++){
                float v = xi[r*28 + c4*4 + j];
                unsigned q = (unsigned)rintf(clip255(ZP1 + v / S1));
                pk |= (q & 0xffu) << (8*j);
            }
        }
        q0u[r*8 + c4] = pk;
    }
    for (int i = tid; i < 100; i += 384){ wlo_s[i] = g_w1lo[i]; whi_s[i] = g_w1hi[i]; }
    if (tid < 20) cc_s[tid] = g_c1c[tid];
    __syncthreads();

    // phase 2: sliding windows
    for (int i = tid; i < 784; i += 384){
        int r = i / 28, xx = i % 28;
        unsigned a = q0u[r*8 + (xx >> 2)];
        unsigned b = q0u[r*8 + (xx >> 2) + 1];
        Wn[i] = __funnelshift_r(a, b, 8*(xx & 3));
    }
    __syncthreads();

    // phase 3: 5x5 window sums
    for (int i = tid; i < 576; i += 384){
        int y = i / 24, xx = i % 24;
        unsigned s = 0;
        #pragma unroll
        for (int ky = 0; ky < 5; ky++){
            s = __dp4a(Wn[(y + ky)*28 + xx], 0x01010101u, s);
            s += (q0u[(y + ky)*8 + ((xx + 4) >> 2)] >> (8*((xx + 4) & 3))) & 0xffu;
        }
        Ps[i] = s;
    }
    __syncthreads();

    // phase 4: conv + fused pool/quant
    if (tid < 360){
        int rr = tid / 30;
        int t  = tid % 30;
        int cg = t / 6, xp = t % 6;
        int x0 = xp * 4;

        unsigned acc[2][4][4] = {};   // [row][col][ch]

        #pragma unroll
        for (int ir = 0; ir < 6; ir++){
            const uint4* w4 = (const uint4*)&Wn[(2*rr + ir)*28 + x0];
            uint4 lo4 = w4[0], hi4 = w4[1];
            unsigned wn[8] = {lo4.x,lo4.y,lo4.z,lo4.w, hi4.x,hi4.y,hi4.z,hi4.w};
            #pragma unroll
            for (int row = 0; row < 2; row++){
                int ky = ir - row;
                if (ky >= 0 && ky <= 4){
                    uint4 wlo = *(const uint4*)&wlo_s[ky*20 + cg*4];
                    uint4 whi = *(const uint4*)&whi_s[ky*20 + cg*4];
                    #pragma unroll
                    for (int c = 0; c < 4; c++){
                        unsigned wl = wn[c], wh = wn[c + 4];
                        acc[row][c][0] = __dp4a(wl, wlo.x, acc[row][c][0]);
                        acc[row][c][1] = __dp4a(wl, wlo.y, acc[row][c][1]);
                        acc[row][c][2] = __dp4a(wl, wlo.z, acc[row][c][2]);
                        acc[row][c][3] = __dp4a(wl, wlo.w, acc[row][c][3]);
                        acc[row][c][0] = __dp4a(wh, whi.x, acc[row][c][0]);
                        acc[row][c][1] = __dp4a(wh, whi.y, acc[row][c][1]);
                        acc[row][c][2] = __dp4a(wh, whi.z, acc[row][c][2]);
                        acc[row][c][3] = __dp4a(wh, whi.w, acc[row][c][3]);
                    }
                }
            }
        }

        float s_w, z_w; get_sz(0, s_w, z_w);
        float Af = S1 * s_w * INV_S2;
        float Bf = Af * z_w;
        float Pv[2][4];
        #pragma unroll
        for (int rw = 0; rw < 2; rw++)
            #pragma unroll
            for (int cl = 0; cl < 4; cl++)
                Pv[rw][cl] = (float)Ps[(2*rr + rw)*24 + x0 + cl];

        unsigned ow0 = 0u, ow1 = 0u;
        #pragma unroll
        for (int c = 0; c < 4; c++){
            float Cc = cc_s[cg*4 + c];   // pre-scaled by INV_S2
            #pragma unroll
            for (int px = 0; px < 2; px++){
                float v0 = Af*(float)(int)acc[0][2*px    ][c] - Bf*Pv[0][2*px    ] + Cc;
                float v1 = Af*(float)(int)acc[0][2*px + 1][c] - Bf*Pv[0][2*px + 1] + Cc;
                float v2 = Af*(float)(int)acc[1][2*px    ][c] - Bf*Pv[1][2*px    ] + Cc;
                float v3 = Af*(float)(int)acc[1][2*px + 1][c] - Bf*Pv[1][2*px + 1] + Cc;
                float m = fmaxf(fmaxf(v0, v1), fmaxf(v2, v3));
                float q = rintf(fmaxf(m, 0.0f));
                unsigned qb = ((unsigned)q & 0xffu) << (8*c);
                if (px == 0) ow0 |= qb; else ow1 |= qb;
            }
        }
        unsigned* dst = (unsigned*)g_act1 + ((img*12 + rr)*5 + cg)*12 + xp*2;
        dst[0] = ow0; dst[1] = ow1;
    }
}

// ---------------- conv2 via int8 mma + quant + pool + rowsum ----------------
__global__ void __launch_bounds__(256) conv2_kernel(){
    __shared__ unsigned Xs[2*12*5*12];
    __shared__ unsigned Bs[128*56];
    __shared__ int offA[128];
    __shared__ unsigned Sw[2*8*8];
    __shared__ float beff_s[C2_CPAD];
    __shared__ unsigned char q2[2*C2_CPAD*64];
    __shared__ int rsum[2];

    int tid = threadIdx.x;
    int imgbase = blockIdx.x * 2;

    {
        const uint4* xsrc = (const uint4*)(g_act1 + imgbase*2880);
        for (int i = tid; i < 360; i += 256) ((uint4*)Xs)[i] = xsrc[i];
    }
    for (int i = tid; i < 128*14; i += 256){
        int g = i / 14, c4 = i % 14;
        uint4 v = make_uint4(0u,0u,0u,0u);
        if (g < 125 && c4 < 13){
            int r = g / 5, p = g % 5;
            v = *(const uint4*)&g_w2q[(p*25 + r)*C2_CPAD + c4*4];
        }
        ((uint4*)Bs)[g*14 + c4] = v;
    }
    if (tid < 128){
        int g = tid;
        int r = (g < 125) ? g/5 : 0, p = (g < 125) ? g%5 : 0;
        int ky = r/5, kx = r%5;
        offA[tid] = ky*60 + p*12 + kx;
    }
    if (tid < C2_CPAD) beff_s[tid] = g_b2eff[tid];
    if (tid < 2) rsum[tid] = 0;
    __syncthreads();

    if (tid < 128){
        int li = tid / 64, t = tid % 64;
        int oy = t / 8, ox = t % 8;
        unsigned s = 0;
        for (int ky = 0; ky < 5; ky++)
            for (int p = 0; p < 5; p++){
                const unsigned* row = &Xs[((li*12 + oy + ky)*5 + p)*12];
                #pragma unroll
                for (int kx = 0; kx < 5; kx++)
                    s = __dp4a(row[ox + kx], 0x01010101u, s);
            }
        Sw[li*64 + oy*8 + ox] = s;
    }

    int w = tid >> 5, l = tid & 31;
    int li = w >> 2, mtile = w & 3;
    int lr = l >> 2, lc = l & 3;
    int oy0 = mtile*2;
    int base0 = li*720 + oy0*60 + lr;
    int base1 = base0 + 60;

    int acc[7][4];
    #pragma unroll
    for (int t = 0; t < 7; t++)
        #pragma unroll
        for (int j = 0; j < 4; j++) acc[t][j] = 0;

    #pragma unroll 1
    for (int step = 0; step < 16; step++){
        int g0 = step*8 + lc;
        int g1 = g0 + 4;
        unsigned a0 = Xs[base0 + offA[g0]];
        unsigned a1 = Xs[base1 + offA[g0]];
        unsigned a2 = Xs[base0 + offA[g1]];
        unsigned a3 = Xs[base1 + offA[g1]];
        const unsigned* b0r = &Bs[g0*56 + lr];
        const unsigned* b1r = &Bs[g1*56 + lr];
        #pragma unroll
        for (int t = 0; t < 7; t++){
            unsigned b0 = b0r[t*8];
            unsigned b1 = b1r[t*8];
            asm volatile(
                "mma.sync.aligned.m16n8k32.row.col.s32.u8.u8.s32 "
                "{%0,%1,%2,%3}, {%4,%5,%6,%7}, {%8,%9}, {%0,%1,%2,%3};"
                : "+r"(acc[t][0]), "+r"(acc[t][1]), "+r"(acc[t][2]), "+r"(acc[t][3])
                : "r"(a0), "r"(a1), "r"(a2), "r"(a3), "r"(b0), "r"(b1));
        }
    }
    __syncthreads();

    {
        float s2w, z2w; get_sz(2, s2w, z2w);
        float S2s = S2C * s2w;
        int zp2 = (int)z2w;
        #pragma unroll
        for (int half = 0; half < 2; half++){
            int oy = oy0 + half, ox = lr;
            int sw = (int)Sw[li*64 + oy*8 + ox];
            #pragma unroll
            for (int t = 0; t < 7; t++){
                #pragma unroll
                for (int j = 0; j < 2; j++){
                    int ch = t*8 + lc*2 + j;
                    if (ch < C2_CPAD){
                        int cval = acc[t][half*2 + j];
                        float val = S2s * (float)(cval - zp2*sw) + beff_s[ch];
                        float v = rintf(fmaxf(val * INV_S3, 0.0f));
                        q2[((li*C2_CPAD + ch)*8 + oy)*8 + ox] = (unsigned char)(unsigned)v;
                    }
                }
            }
        }
    }
    __syncthreads();

    // pool 2x2 + per-image rowsum
    int lsum0 = 0, lsum1 = 0;
    for (int i = tid; i < 1600; i += 256){
        int im = i / 800, rest = i % 800;
        int ch = rest / 16, pr = (rest % 16) / 4, pc = rest % 4;
        const unsigned char* bp = q2 + ((im*C2_CPAD + ch)*8 + 2*pr)*8 + 2*pc;
        unsigned char m = max(max(bp[0], bp[1]), max(bp[8], bp[9]));
        g_act2[((imgbase + im)*50 + ch)*16 + pr*4 + pc] = m;
        if (im == 0) lsum0 += m; else lsum1 += m;
    }
    #pragma unroll
    for (int off = 16; off; off >>= 1){
        lsum0 += __shfl_down_sync(0xffffffffu, lsum0, off);
        lsum1 += __shfl_down_sync(0xffffffffu, lsum1, off);
    }
    if ((tid & 31) == 0){
        if (lsum0) atomicAdd(&rsum[0], lsum0);
        if (lsum1) atomicAdd(&rsum[1], lsum1);
    }
    __syncthreads();
    if (tid < 2) g_rowsum[imgbase + tid] = rsum[tid];
}

// ---------------- fc1 via int8 mma + quant + dequant ----------------
// M=4096, N=512(pad), K=800. Block tile 64x64, 256 thr (8 warps: 2M x 4N), K chunks of 160B.
__global__ void __launch_bounds__(256) fc1_kernel(){
    __shared__ unsigned As[64*44];    // [m][k u32], stride 44 (conflict-free: 12*lr+lc)
    __shared__ unsigned Bs[40*72];    // [k u32][n], stride 72 (conflict-free: 8*lc+lr)

    int tid = threadIdx.x;
    int w = tid >> 5, l = tid & 31;
    int lr = l >> 2, lc = l & 3;
    int m0 = blockIdx.x * 64, n0 = blockIdx.y * 64;
    int wm = (w & 1) * 32;
    int wn = (w >> 1) * 16;

    int acc[2][2][4];
    #pragma unroll
    for (int mt = 0; mt < 2; mt++)
        #pragma unroll
        for (int nt = 0; nt < 2; nt++)
            #pragma unroll
            for (int j = 0; j < 4; j++) acc[mt][nt][j] = 0;

    const unsigned* Xg = (const unsigned*)g_act2;

    #pragma unroll 1
    for (int chunk = 0; chunk < 5; chunk++){
        for (int i = tid; i < 640; i += 256){
            int r = i / 10, c4 = i % 10;
            uint4 v = *(const uint4*)&Xg[(m0 + r)*200 + chunk*40 + c4*4];
            *(uint4*)&As[r*44 + c4*4] = v;
        }
        for (int i = tid; i < 640; i += 256){
            int kr = i / 16, c4 = i % 16;
            uint4 v = *(const uint4*)&g_fc1q[(chunk*40 + kr)*512 + n0 + c4*4];
            *(uint4*)&Bs[kr*72 + c4*4] = v;
        }
        __syncthreads();

        #pragma unroll
        for (int s = 0; s < 5; s++){
            int g = s*8;
            unsigned a[2][4];
            #pragma unroll
            for (int mt = 0; mt < 2; mt++){
                int r0 = wm + mt*16 + lr;
                a[mt][0] = As[r0*44 + g + lc];
                a[mt][1] = As[(r0 + 8)*44 + g + lc];
                a[mt][2] = As[r0*44 + g + 4 + lc];
                a[mt][3] = As[(r0 + 8)*44 + g + 4 + lc];
            }
            unsigned b[2][2];
            #pragma unroll
            for (int nt = 0; nt < 2; nt++){
                int nn = wn + nt*8 + lr;
                b[nt][0] = Bs[(g + lc)*72 + nn];
                b[nt][1] = Bs[(g + 4 + lc)*72 + nn];
            }
            #pragma unroll
            for (int mt = 0; mt < 2; mt++)
                #pragma unroll
                for (int nt = 0; nt < 2; nt++){
                    asm volatile(
                        "mma.sync.aligned.m16n8k32.row.col.s32.u8.u8.s32 "
                        "{%0,%1,%2,%3}, {%4,%5,%6,%7}, {%8,%9}, {%0,%1,%2,%3};"
                        : "+r"(acc[mt][nt][0]), "+r"(acc[mt][nt][1]),
                          "+r"(acc[mt][nt][2]), "+r"(acc[mt][nt][3])
                        : "r"(a[mt][0]), "r"(a[mt][1]), "r"(a[mt][2]), "r"(a[mt][3]),
                          "r"(b[nt][0]), "r"(b[nt][1]));
                }
        }
        __syncthreads();
    }

    float s3w, z3w; get_sz(4, s3w, z3w);
    float S3s = S3C * s3w;
    int zp3 = (int)z3w;

    #pragma unroll
    for (int mt = 0; mt < 2; mt++){
        int mr0 = m0 + wm + mt*16 + lr;
        int rs0 = g_rowsum[mr0];
        int rs1 = g_rowsum[mr0 + 8];
        #pragma unroll
        for (int nt = 0; nt < 2; nt++){
            int nb = n0 + wn + nt*8 + 2*lc;
            #pragma unroll
            for (int j = 0; j < 2; j++){
                int n = nb + j;
                if (n < 500){
                    float y0 = S3s * (float)(acc[mt][nt][j]     - zp3 * rs0) + g_b3eff[n];
                    float v0 = rintf(fmaxf(y0 * INV_S4, 0.0f));
                    g_xf[mr0*500 + n] = S4 * (float)((unsigned)v0 & 0xffu);
                    float y1 = S3s * (float)(acc[mt][nt][2 + j] - zp3 * rs1) + g_b3eff[n];
                    float v1 = rintf(fmaxf(y1 * INV_S4, 0.0f));
                    g_xf[(mr0 + 8)*500 + n] = S4 * (float)((unsigned)v1 & 0xffu);
                }
            }
        }
    }
}

// ---------------- fc2 + log_softmax ----------------
__global__ void __launch_bounds__(128) fc2_kernel(const float* __restrict__ w,
                                                  const float* __restrict__ bias,
                                                  float* __restrict__ out){
    __shared__ float ws[5000];
    __shared__ float bsh[10];
    int tid = threadIdx.x;
    for (int i = tid; i < 5000; i += 128){
        int j = i / 500, k = i % 500;
        ws[k*10 + j] = w[i];
    }
    if (tid < 10) bsh[tid] = bias[tid];
    __syncthreads();

    int warp = tid / 32, lane = tid % 32;
    int row = blockIdx.x*4 + warp;
    float acc[10];
    #pragma unroll
    for (int j = 0; j < 10; j++) acc[j] = 0.0f;

    for (int k = lane; k < 500; k += 32){
        float xv = g_xf[row*500 + k];
        const float* wr = ws + k*10;
        #pragma unroll
        for (int j = 0; j < 10; j++) acc[j] += xv * wr[j];
    }
    #pragma unroll
    for (int j = 0; j < 10; j++){
        #pragma unroll
        for (int off = 16; off; off >>= 1)
            acc[j] += __shfl_down_sync(0xffffffffu, acc[j], off);
    }
    if (lane == 0){
        float l[10], m = -1e30f;
        #pragma unroll
        for (int j = 0; j < 10; j++){ l[j] = acc[j] + bsh[j]; m = fmaxf(m, l[j]); }
        float s = 0.0f;
        #pragma unroll
        for (int j = 0; j < 10; j++) s += expf(l[j] - m);
        float ls = logf(s);
        #pragma unroll
        for (int j = 0; j < 10; j++) out[row*10 + j] = l[j] - m - ls;
    }
}

// ---------------- launch ----------------
extern "C" void kernel_launch(void* const* d_in, const int* in_sizes, int n_in,
                              void* d_out, int out_size){
    const float* x   = (const float*)d_in[0];
    const float* c1w = (const float*)d_in[1];
    const float* c1b = (const float*)d_in[2];
    const float* c2w = (const float*)d_in[3];
    const float* c2b = (const float*)d_in[4];
    const float* f1w = (const float*)d_in[5];
    const float* f1b = (const float*)d_in[6];
    const float* f2w = (const float*)d_in[7];
    const float* f2b = (const float*)d_in[8];

    init_mm_kernel<<<1, 32>>>();
    minmax_kernel<<<72, 256>>>(c1w, c1b, c2w, c2b, f1w, f1b);
    effs_kernel<<<429, 256>>>(c1w, c1b, c2w, c2b, f1w, f1b);
    conv1_kernel<<<BATCH, 384>>>(x);
    conv2_kernel<<<BATCH/2, 256>>>();
    fc1_kernel<<<dim3(BATCH/64, 8), 256>>>();
    fc2_kernel<<<BATCH/4, 128>>>(f2w, f2b, (float*)d_out);
}

// round 8
// speedup vs baseline: 2.9549x; 1.0389x over previous
#include <cuda_runtime.h>
#include <cstdint>

// ---------------- constants (STATS are fixed) ----------------
#define S1 (3.5f/255.0f)   // conv1 stat (-0.5, 3.0)
#define ZP1 36.0f          // trunc(0.5/S1)
#define INV_S2 42.5f       // 255/6  (exact)
#define INV_S3 31.875f     // 255/8  (exact)
#define INV_S4 25.5f       // 255/10 (exact)
#define S4 (10.0f/255.0f)
#define S2C (6.0f/255.0f)
#define S3C (8.0f/255.0f)

#define BATCH 4096
#define C2_CPAD 52

// ---------------- device scratch ----------------
// statically armed for the first (correctness) call; fc2 re-arms for the next call
__device__ unsigned g_mmkey[12] = {0xFFFFFFFFu,0u, 0xFFFFFFFFu,0u, 0xFFFFFFFFu,0u,
                                   0xFFFFFFFFu,0u, 0xFFFFFFFFu,0u, 0xFFFFFFFFu,0u};
__device__ __align__(16) unsigned g_w1lo[5*20];
__device__ __align__(16) unsigned g_w1hi[5*20];
__device__ float g_c1c[20];                              // conv1 const, pre-scaled by INV_S2
__device__ __align__(16) unsigned g_w2q[5*25*C2_CPAD];  // conv2 wq packed: [p][r=ky*5+kx][c]
__device__ float g_b2eff[C2_CPAD];
__device__ __align__(16) unsigned g_fc1q[200*512];      // fc1 wq packed: [kp=200][n pad 512]
__device__ float g_b3eff[512];
__device__ __align__(16) unsigned char g_act1[BATCH*12*5*12*4];
__device__ __align__(16) unsigned char g_act2[BATCH*50*4*4];
__device__ int g_rowsum[BATCH];
__device__ float g_xf[BATCH*500];

// ---------------- helpers ----------------
__device__ __forceinline__ float clip255(float v){ return fminf(fmaxf(v, 0.0f), 255.0f); }
__device__ __forceinline__ unsigned f2key(float f){
    unsigned u = __float_as_uint(f);
    return (u & 0x80000000u) ? ~u : (u | 0x80000000u);
}
__device__ __forceinline__ float key2f(unsigned k){
    return __uint_as_float((k & 0x80000000u) ? (k & 0x7fffffffu) : ~k);
}
__device__ __forceinline__ void get_sz(int t, float& scale, float& zp){
    float mn = key2f(g_mmkey[2*t]);
    float mx = key2f(g_mmkey[2*t+1]);
    scale = (mx - mn) / 255.0f;
    zp = truncf(clip255(-mn / scale));
}
// reciprocal form: one division per thread, multiplies thereafter
__device__ __forceinline__ void get_szi(int t, float& inv, float& zp){
    float mn = key2f(g_mmkey[2*t]);
    float mx = key2f(g_mmkey[2*t+1]);
    float scale = (mx - mn) / 255.0f;
    inv = 255.0f / (mx - mn);
    zp = truncf(clip255(-mn / scale));
}
__device__ __forceinline__ float qroundi(float v, float inv, float zp){
    return rintf(clip255(zp + v * inv));
}

// ---------------- min/max over 6 param tensors ----------------
__global__ void minmax_kernel(const float* __restrict__ c1w, const float* __restrict__ c1b,
                              const float* __restrict__ c2w, const float* __restrict__ c2b,
                              const float* __restrict__ f1w, const float* __restrict__ f1b){
    __shared__ unsigned smn[256], smx[256];
    int b = blockIdx.x, tid = threadIdx.x;
    const float* p; int n, t, sub, nb;
    if (b < 64)      { t = 4; p = f1w; n = 400000; sub = b;      nb = 64; }
    else if (b < 68) { t = 2; p = c2w; n = 25000;  sub = b - 64; nb = 4;  }
    else if (b == 68){ t = 0; p = c1w; n = 500;    sub = 0;      nb = 1;  }
    else if (b == 69){ t = 1; p = c1b; n = 20;     sub = 0;      nb = 1;  }
    else if (b == 70){ t = 3; p = c2b; n = 50;     sub = 0;      nb = 1;  }
    else             { t = 5; p = f1b; n = 500;    sub = 0;      nb = 1;  }

    unsigned lmin = 0xFFFFFFFFu, lmax = 0u;
    for (int i = sub*256 + tid; i < n; i += nb*256){
        unsigned k = f2key(p[i]);
        lmin = min(lmin, k); lmax = max(lmax, k);
    }
    smn[tid] = lmin; smx[tid] = lmax;
    __syncthreads();
    for (int s = 128; s; s >>= 1){
        if (tid < s){
            smn[tid] = min(smn[tid], smn[tid+s]);
            smx[tid] = max(smx[tid], smx[tid+s]);
        }
        __syncthreads();
    }
    if (tid == 0){
        atomicMin(&g_mmkey[2*t],   smn[0]);
        atomicMax(&g_mmkey[2*t+1], smx[0]);
    }
}

// ---------------- build packed weights / constants ----------------
__global__ void effs_kernel(const float* __restrict__ c1w, const float* __restrict__ c1b,
                            const float* __restrict__ c2w, const float* __restrict__ c2b,
                            const float* __restrict__ f1w, const float* __restrict__ f1b){
    int idx = blockIdx.x*blockDim.x + threadIdx.x;
    if (idx < 100){
        int ky = idx / 20, ch = idx % 20;
        float iv, z; get_szi(0, iv, z);
        unsigned lo = 0u;
        #pragma unroll
        for (int j = 0; j < 4; j++){
            unsigned wq = (unsigned)qroundi(c1w[ch*25 + ky*5 + j], iv, z);
            lo |= (wq & 0xffu) << (8*j);
        }
        g_w1lo[idx] = lo;
        g_w1hi[idx] = (unsigned)qroundi(c1w[ch*25 + ky*5 + 4], iv, z) & 0xffu;
    } else if (idx < 120){
        int ch = idx - 100;
        float iv, z; get_szi(0, iv, z);
        float s, zz; get_sz(0, s, zz);
        float wsum = 0.0f;
        for (int k = 0; k < 25; k++) wsum += qroundi(c1w[ch*25 + k], iv, z);
        float ivb, zb; get_szi(1, ivb, zb);
        float sb, zb2; get_sz(1, sb, zb2);
        float beff = sb * (qroundi(c1b[ch], ivb, zb) + zb);
        g_c1c[ch] = (beff + (S1 * s) * (900.0f * z - 36.0f * wsum)) * INV_S2;
    } else if (idx < 6620){                               // conv2 wq packed [p][r][c]
        int e = idx - 120;
        int p = e / (25*C2_CPAD), r = (e / C2_CPAD) % 25, c = e % C2_CPAD;
        unsigned pk = 0u;
        if (c < 50){
            float iv, z; get_szi(2, iv, z);
            #pragma unroll
            for (int j = 0; j < 4; j++){
                int ci = p*4 + j;
                unsigned wq = (unsigned)qroundi(c2w[c*500 + ci*25 + r], iv, z);
                pk |= (wq & 0xffu) << (8*j);
            }
        }
        g_w2q[e] = pk;
    } else if (idx < 6672){
        int c = idx - 6620;
        float val = 0.0f;
        if (c < 50){
            float s, z; get_sz(3, s, z);
            val = s * (qroundi(c2b[c], 255.0f/( (key2f(g_mmkey[7]) - key2f(g_mmkey[6])) ), z) + z);
        }
        g_b2eff[c] = val;
    } else if (idx < 109072){
        int e = idx - 6672;
        int kp = e / 512, n = e % 512;
        unsigned pk = 0u;
        if (n < 500){
            float iv, z; get_szi(4, iv, z);
            #pragma unroll
            for (int j = 0; j < 4; j++){
                int k = kp*4 + j;
                unsigned wq = (unsigned)qroundi(f1w[n*800 + k], iv, z);
                pk |= (wq & 0xffu) << (8*j);
            }
        }
        g_fc1q[e] = pk;
    } else if (idx < 109584){
        int n = idx - 109072;
        float val = 0.0f;
        if (n < 500){
            float iv, z; get_szi(5, iv, z);
            float s, zz; get_sz(5, s, zz);
            val = s * (qroundi(f1b[n], iv, z) + z);
        }
        g_b3eff[n] = val;
    }
}

// ---------------- conv1 via dp4a, fused integer pool + quant ----------------
// one image per block, 384 threads, 360 compute: thread -> (rr 0..11, cg 0..4, xp 0..5)
__global__ void __launch_bounds__(384, 3) conv1_kernel(const float* __restrict__ x){
    __shared__ unsigned q0u[28*8];        // q0 bytes, 8 u32 per row (last = pad 0)
    __shared__ unsigned Wn[28*28];        // sliding 4-byte windows per row
    __shared__ unsigned Ps[24*24];        // 5x5 window sums of q0
    __shared__ unsigned wlo_s[100], whi_s[100];
    __shared__ float cc_s[20];

    int img = blockIdx.x, tid = threadIdx.x;
    const float* xi = x + img*784;

    // phase 1: quantize input to u8, packed u32
    if (tid < 224){
        int r = tid / 8, c4 = tid % 8;
        unsigned pk = 0u;
        if (c4 < 7){
            #pragma unroll
            for (int j = 0; j < 4; j++){
                float v = xi[r*28 + c4*4 + j];
                unsigned q = (unsigned)rintf(clip255(ZP1 + v / S1));
                pk |= (q & 0xffu) << (8*j);
            }
        }
        q0u[r*8 + c4] = pk;
    }
    for (int i = tid; i < 100; i += 384){ wlo_s[i] = g_w1lo[i]; whi_s[i] = g_w1hi[i]; }
    if (tid < 20) cc_s[tid] = g_c1c[tid];
    __syncthreads();

    // phase 2: sliding windows
    for (int i = tid; i < 784; i += 384){
        int r = i / 28, xx = i % 28;
        unsigned a = q0u[r*8 + (xx >> 2)];
        unsigned b = q0u[r*8 + (xx >> 2) + 1];
        Wn[i] = __funnelshift_r(a, b, 8*(xx & 3));
    }
    __syncthreads();

    // phase 3: 5x5 window sums
    for (int i = tid; i < 576; i += 384){
        int y = i / 24, xx = i % 24;
        unsigned s = 0;
        #pragma unroll
        for (int ky = 0; ky < 5; ky++){
            s = __dp4a(Wn[(y + ky)*28 + xx], 0x01010101u, s);
            s += (q0u[(y + ky)*8 + ((xx + 4) >> 2)] >> (8*((xx + 4) & 3))) & 0xffu;
        }
        Ps[i] = s;
    }
    __syncthreads();

    // phase 4: conv + integer pool + quant
    if (tid < 360){
        int rr = tid / 30;
        int t  = tid % 30;
        int cg = t / 6, xp = t % 6;
        int x0 = xp * 4;

        unsigned acc[2][4][4] = {};   // [row][col][ch]

        #pragma unroll
        for (int ir = 0; ir < 6; ir++){
            const uint4* w4 = (const uint4*)&Wn[(2*rr + ir)*28 + x0];
            uint4 lo4 = w4[0], hi4 = w4[1];
            unsigned wn[8] = {lo4.x,lo4.y,lo4.z,lo4.w, hi4.x,hi4.y,hi4.z,hi4.w};
            #pragma unroll
            for (int row = 0; row < 2; row++){
                int ky = ir - row;
                if (ky >= 0 && ky <= 4){
                    uint4 wlo = *(const uint4*)&wlo_s[ky*20 + cg*4];
                    uint4 whi = *(const uint4*)&whi_s[ky*20 + cg*4];
                    #pragma unroll
                    for (int c = 0; c < 4; c++){
                        unsigned wl = wn[c], wh = wn[c + 4];
                        acc[row][c][0] = __dp4a(wl, wlo.x, acc[row][c][0]);
                        acc[row][c][1] = __dp4a(wl, wlo.y, acc[row][c][1]);
                        acc[row][c][2] = __dp4a(wl, wlo.z, acc[row][c][2]);
                        acc[row][c][3] = __dp4a(wl, wlo.w, acc[row][c][3]);
                        acc[row][c][0] = __dp4a(wh, whi.x, acc[row][c][0]);
                        acc[row][c][1] = __dp4a(wh, whi.y, acc[row][c][1]);
                        acc[row][c][2] = __dp4a(wh, whi.z, acc[row][c][2]);
                        acc[row][c][3] = __dp4a(wh, whi.w, acc[row][c][3]);
                    }
                }
            }
        }

        float s_w, z_w; get_sz(0, s_w, z_w);
        float Af = S1 * s_w * INV_S2;
        int zpi = (int)z_w;
        // zp * windowsum per position (8 IMAD)
        int ZP[2][4];
        #pragma unroll
        for (int rw = 0; rw < 2; rw++)
            #pragma unroll
            for (int cl = 0; cl < 4; cl++)
                ZP[rw][cl] = zpi * (int)Ps[(2*rr + rw)*24 + x0 + cl];

        unsigned ow0 = 0u, ow1 = 0u;
        #pragma unroll
        for (int c = 0; c < 4; c++){
            float Cc = cc_s[cg*4 + c];   // pre-scaled by INV_S2
            #pragma unroll
            for (int px = 0; px < 2; px++){
                int i0 = (int)acc[0][2*px    ][c] - ZP[0][2*px    ];
                int i1 = (int)acc[0][2*px + 1][c] - ZP[0][2*px + 1];
                int i2 = (int)acc[1][2*px    ][c] - ZP[1][2*px    ];
                int i3 = (int)acc[1][2*px + 1][c] - ZP[1][2*px + 1];
                int im = max(max(i0, i1), max(i2, i3));
                float q = rintf(fmaxf(Af*(float)im + Cc, 0.0f));
                unsigned qb = ((unsigned)q & 0xffu) << (8*c);
                if (px == 0) ow0 |= qb; else ow1 |= qb;
            }
        }
        unsigned* dst = (unsigned*)g_act1 + ((img*12 + rr)*5 + cg)*12 + xp*2;
        dst[0] = ow0; dst[1] = ow1;
    }
}

// ---------------- conv2 via int8 mma + quant + pool + rowsum ----------------
__global__ void __launch_bounds__(256) conv2_kernel(){
    __shared__ unsigned Xs[2*12*5*12];
    __shared__ unsigned Bs[128*56];
    __shared__ int offA[128];
    __shared__ unsigned Sw[2*8*8];
    __shared__ float beff_s[C2_CPAD];
    __shared__ unsigned char q2[2*C2_CPAD*64];
    __shared__ int rsum[2];

    int tid = threadIdx.x;
    int imgbase = blockIdx.x * 2;

    {
        const uint4* xsrc = (const uint4*)(g_act1 + imgbase*2880);
        for (int i = tid; i < 360; i += 256) ((uint4*)Xs)[i] = xsrc[i];
    }
    for (int i = tid; i < 128*14; i += 256){
        int g = i / 14, c4 = i % 14;
        uint4 v = make_uint4(0u,0u,0u,0u);
        if (g < 125 && c4 < 13){
            int r = g / 5, p = g % 5;
            v = *(const uint4*)&g_w2q[(p*25 + r)*C2_CPAD + c4*4];
        }
        ((uint4*)Bs)[g*14 + c4] = v;
    }
    if (tid < 128){
        int g = tid;
        int r = (g < 125) ? g/5 : 0, p = (g < 125) ? g%5 : 0;
        int ky = r/5, kx = r%5;
        offA[tid] = ky*60 + p*12 + kx;
    }
    if (tid < C2_CPAD) beff_s[tid] = g_b2eff[tid];
    if (tid < 2) rsum[tid] = 0;
    __syncthreads();

    if (tid < 128){
        int li = tid / 64, t = tid % 64;
        int oy = t / 8, ox = t % 8;
        unsigned s = 0;
        for (int ky = 0; ky < 5; ky++)
            for (int p = 0; p < 5; p++){
                const unsigned* row = &Xs[((li*12 + oy + ky)*5 + p)*12];
                #pragma unroll
                for (int kx = 0; kx < 5; kx++)
                    s = __dp4a(row[ox + kx], 0x01010101u, s);
            }
        Sw[li*64 + oy*8 + ox] = s;
    }

    int w = tid >> 5, l = tid & 31;
    int li = w >> 2, mtile = w & 3;
    int lr = l >> 2, lc = l & 3;
    int oy0 = mtile*2;
    int base0 = li*720 + oy0*60 + lr;
    int base1 = base0 + 60;

    int acc[7][4];
    #pragma unroll
    for (int t = 0; t < 7; t++)
        #pragma unroll
        for (int j = 0; j < 4; j++) acc[t][j] = 0;

    #pragma unroll 1
    for (int step = 0; step < 16; step++){
        int g0 = step*8 + lc;
        int g1 = g0 + 4;
        unsigned a0 = Xs[base0 + offA[g0]];
        unsigned a1 = Xs[base1 + offA[g0]];
        unsigned a2 = Xs[base0 + offA[g1]];
        unsigned a3 = Xs[base1 + offA[g1]];
        const unsigned* b0r = &Bs[g0*56 + lr];
        const unsigned* b1r = &Bs[g1*56 + lr];
        #pragma unroll
        for (int t = 0; t < 7; t++){
            unsigned b0 = b0r[t*8];
            unsigned b1 = b1r[t*8];
            asm volatile(
                "mma.sync.aligned.m16n8k32.row.col.s32.u8.u8.s32 "
                "{%0,%1,%2,%3}, {%4,%5,%6,%7}, {%8,%9}, {%0,%1,%2,%3};"
                : "+r"(acc[t][0]), "+r"(acc[t][1]), "+r"(acc[t][2]), "+r"(acc[t][3])
                : "r"(a0), "r"(a1), "r"(a2), "r"(a3), "r"(b0), "r"(b1));
        }
    }
    __syncthreads();

    {
        float s2w, z2w; get_sz(2, s2w, z2w);
        float S2s = S2C * s2w;
        int zp2 = (int)z2w;
        #pragma unroll
        for (int half = 0; half < 2; half++){
            int oy = oy0 + half, ox = lr;
            int sw = (int)Sw[li*64 + oy*8 + ox];
            #pragma unroll
            for (int t = 0; t < 7; t++){
                #pragma unroll
                for (int j = 0; j < 2; j++){
                    int ch = t*8 + lc*2 + j;
                    if (ch < C2_CPAD){
                        int cval = acc[t][half*2 + j];
                        float val = S2s * (float)(cval - zp2*sw) + beff_s[ch];
                        float v = rintf(fmaxf(val * INV_S3, 0.0f));
                        q2[((li*C2_CPAD + ch)*8 + oy)*8 + ox] = (unsigned char)(unsigned)v;
                    }
                }
            }
        }
    }
    __syncthreads();

    // pool 2x2 + per-image rowsum
    int lsum0 = 0, lsum1 = 0;
    for (int i = tid; i < 1600; i += 256){
        int im = i / 800, rest = i % 800;
        int ch = rest / 16, pr = (rest % 16) / 4, pc = rest % 4;
        const unsigned char* bp = q2 + ((im*C2_CPAD + ch)*8 + 2*pr)*8 + 2*pc;
        unsigned char m = max(max(bp[0], bp[1]), max(bp[8], bp[9]));
        g_act2[((imgbase + im)*50 + ch)*16 + pr*4 + pc] = m;
        if (im == 0) lsum0 += m; else lsum1 += m;
    }
    #pragma unroll
    for (int off = 16; off; off >>= 1){
        lsum0 += __shfl_down_sync(0xffffffffu, lsum0, off);
        lsum1 += __shfl_down_sync(0xffffffffu, lsum1, off);
    }
    if ((tid & 31) == 0){
        if (lsum0) atomicAdd(&rsum[0], lsum0);
        if (lsum1) atomicAdd(&rsum[1], lsum1);
    }
    __syncthreads();
    if (tid < 2) g_rowsum[imgbase + tid] = rsum[tid];
}

// ---------------- fc1 via int8 mma + quant + dequant ----------------
__global__ void __launch_bounds__(256) fc1_kernel(){
    __shared__ unsigned As[64*44];
    __shared__ unsigned Bs[40*72];

    int tid = threadIdx.x;
    int w = tid >> 5, l = tid & 31;
    int lr = l >> 2, lc = l & 3;
    int m0 = blockIdx.x * 64, n0 = blockIdx.y * 64;
    int wm = (w & 1) * 32;
    int wn = (w >> 1) * 16;

    int acc[2][2][4];
    #pragma unroll
    for (int mt = 0; mt < 2; mt++)
        #pragma unroll
        for (int nt = 0; nt < 2; nt++)
            #pragma unroll
            for (int j = 0; j < 4; j++) acc[mt][nt][j] = 0;

    const unsigned* Xg = (const unsigned*)g_act2;

    #pragma unroll 1
    for (int chunk = 0; chunk < 5; chunk++){
        for (int i = tid; i < 640; i += 256){
            int r = i / 10, c4 = i % 10;
            uint4 v = *(const uint4*)&Xg[(m0 + r)*200 + chunk*40 + c4*4];
            *(uint4*)&As[r*44 + c4*4] = v;
        }
        for (int i = tid; i < 640; i += 256){
            int kr = i / 16, c4 = i % 16;
            uint4 v = *(const uint4*)&g_fc1q[(chunk*40 + kr)*512 + n0 + c4*4];
            *(uint4*)&Bs[kr*72 + c4*4] = v;
        }
        __syncthreads();

        #pragma unroll
        for (int s = 0; s < 5; s++){
            int g = s*8;
            unsigned a[2][4];
            #pragma unroll
            for (int mt = 0; mt < 2; mt++){
                int r0 = wm + mt*16 + lr;
                a[mt][0] = As[r0*44 + g + lc];
                a[mt][1] = As[(r0 + 8)*44 + g + lc];
                a[mt][2] = As[r0*44 + g + 4 + lc];
                a[mt][3] = As[(r0 + 8)*44 + g + 4 + lc];
            }
            unsigned b[2][2];
            #pragma unroll
            for (int nt = 0; nt < 2; nt++){
                int nn = wn + nt*8 + lr;
                b[nt][0] = Bs[(g + lc)*72 + nn];
                b[nt][1] = Bs[(g + 4 + lc)*72 + nn];
            }
            #pragma unroll
            for (int mt = 0; mt < 2; mt++)
                #pragma unroll
                for (int nt = 0; nt < 2; nt++){
                    asm volatile(
                        "mma.sync.aligned.m16n8k32.row.col.s32.u8.u8.s32 "
                        "{%0,%1,%2,%3}, {%4,%5,%6,%7}, {%8,%9}, {%0,%1,%2,%3};"
                        : "+r"(acc[mt][nt][0]), "+r"(acc[mt][nt][1]),
                          "+r"(acc[mt][nt][2]), "+r"(acc[mt][nt][3])
                        : "r"(a[mt][0]), "r"(a[mt][1]), "r"(a[mt][2]), "r"(a[mt][3]),
                          "r"(b[nt][0]), "r"(b[nt][1]));
                }
        }
        __syncthreads();
    }

    float s3w, z3w; get_sz(4, s3w, z3w);
    float S3s = S3C * s3w;
    int zp3 = (int)z3w;

    #pragma unroll
    for (int mt = 0; mt < 2; mt++){
        int mr0 = m0 + wm + mt*16 + lr;
        int rs0 = g_rowsum[mr0];
        int rs1 = g_rowsum[mr0 + 8];
        #pragma unroll
        for (int nt = 0; nt < 2; nt++){
            int nb = n0 + wn + nt*8 + 2*lc;
            #pragma unroll
            for (int j = 0; j < 2; j++){
                int n = nb + j;
                if (n < 500){
                    float y0 = S3s * (float)(acc[mt][nt][j]     - zp3 * rs0) + g_b3eff[n];
                    float v0 = rintf(fmaxf(y0 * INV_S4, 0.0f));
                    g_xf[mr0*500 + n] = S4 * (float)((unsigned)v0 & 0xffu);
                    float y1 = S3s * (float)(acc[mt][nt][2 + j] - zp3 * rs1) + g_b3eff[n];
                    float v1 = rintf(fmaxf(y1 * INV_S4, 0.0f));
                    g_xf[(mr0 + 8)*500 + n] = S4 * (float)((unsigned)v1 & 0xffu);
                }
            }
        }
    }
}

// ---------------- fc2 + log_softmax (+ re-arm minmax keys for next run) ----------------
__global__ void __launch_bounds__(128) fc2_kernel(const float* __restrict__ w,
                                                  const float* __restrict__ bias,
                                                  float* __restrict__ out){
    __shared__ float ws[5000];
    __shared__ float bsh[10];
    int tid = threadIdx.x;

    // re-arm g_mmkey for the next kernel_launch call (all key consumers ran in earlier launches)
    if (blockIdx.x == 0 && tid < 12)
        g_mmkey[tid] = (tid & 1) ? 0u : 0xFFFFFFFFu;

    for (int i = tid; i < 5000; i += 128) ws[i] = w[i];   // linear staging, no div/mod
    if (tid < 10) bsh[tid] = bias[tid];
    __syncthreads();

    int warp = tid / 32, lane = tid % 32;
    int row = blockIdx.x*4 + warp;
    float acc[10];
    #pragma unroll
    for (int j = 0; j < 10; j++) acc[j] = 0.0f;

    for (int k = lane; k < 500; k += 32){
        float xv = g_xf[row*500 + k];
        #pragma unroll
        for (int j = 0; j < 10; j++) acc[j] += xv * ws[j*500 + k];
    }
    #pragma unroll
    for (int j = 0; j < 10; j++){
        #pragma unroll
        for (int off = 16; off; off >>= 1)
            acc[j] += __shfl_down_sync(0xffffffffu, acc[j], off);
    }
    if (lane == 0){
        float l[10], m = -1e30f;
        #pragma unroll
        for (int j = 0; j < 10; j++){ l[j] = acc[j] + bsh[j]; m = fmaxf(m, l[j]); }
        float s = 0.0f;
        #pragma unroll
        for (int j = 0; j < 10; j++) s += expf(l[j] - m);
        float ls = logf(s);
        #pragma unroll
        for (int j = 0; j < 10; j++) out[row*10 + j] = l[j] - m - ls;
    }
}

// ---------------- launch ----------------
extern "C" void kernel_launch(void* const* d_in, const int* in_sizes, int n_in,
                              void* d_out, int out_size){
    const float* x   = (const float*)d_in[0];
    const float* c1w = (const float*)d_in[1];
    const float* c1b = (const float*)d_in[2];
    const float* c2w = (const float*)d_in[3];
    const float* c2b = (const float*)d_in[4];
    const float* f1w = (const float*)d_in[5];
    const float* f1b = (const float*)d_in[6];
    const float* f2w = (const float*)d_in[7];
    const float* f2b = (const float*)d_in[8];

    minmax_kernel<<<72, 256>>>(c1w, c1b, c2w, c2b, f1w, f1b);
    effs_kernel<<<429, 256>>>(c1w, c1b, c2w, c2b, f1w, f1b);
    conv1_kernel<<<BATCH, 384>>>(x);
    conv2_kernel<<<BATCH/2, 256>>>();
    fc1_kernel<<<dim3(BATCH/64, 8), 256>>>();
    fc2_kernel<<<BATCH/4, 128>>>(f2w, f2b, (float*)d_out);
}